// round 2
// baseline (speedup 1.0000x reference)
#include <cuda_runtime.h>
#include <cuda_bf16.h>
#include <cstddef>

// ---------------------------------------------------------------------------
// MPNN layer, fp32, decomposed into fused two-layer tile-GEMMs.
//   B=50000 nodes, K=32 neighbors, D=128, E=32.
// Kernel 1 (self_kernel):  g_aself = h_self @ eW1[0:128] + eb1        [B,128]
// Kernel 2 (edge_kernel):  per 4-node tile (128 rows of neighbors):
//      y = relu(g_aself + [h_nei|e_ij] @ eW1[128:288])                (K=160)
//      z = relu(y @ eW2 + eb2)                                        (K=128)
//      g_mi[node] = sum_k mask * z
// Kernel 3 (node_kernel):  h1 = relu([h_self|g_mi] @ nW1 + nb1); out = relu(h1@nW2+nb2)
// All GEMMs: 128x128 tile, 256 threads, 8x8 micro-tile, packed fma.rn.f32x2.
// ---------------------------------------------------------------------------

#define B_  50000
#define K_  32
#define D_  128
#define E_  32

// scratch (allocation-free rule: __device__ globals)
__device__ float g_aself[(size_t)B_ * D_];
__device__ float g_mi[(size_t)B_ * D_];

// ---- packed f32x2 helpers --------------------------------------------------
__device__ __forceinline__ unsigned long long dup2(float b) {
    unsigned long long r;
    asm("mov.b64 %0, {%1, %1};" : "=l"(r) : "f"(b));
    return r;
}
__device__ __forceinline__ void fma2(unsigned long long &d, unsigned long long a,
                                     unsigned long long b) {
    asm("fma.rn.f32x2 %0, %1, %2, %0;" : "+l"(d) : "l"(a), "l"(b));
}
__device__ __forceinline__ float2 unpk(unsigned long long v) {
    float2 r;
    asm("mov.b64 {%0, %1}, %2;" : "=f"(r.x), "=f"(r.y) : "l"(v));
    return r;
}

// One k-step of the 8x8 micro-tile (pairs packed along M).
// xs -> 8 consecutive floats X^T[k][m0..m0+7] (stride-132 rows, 16B aligned)
// ws -> 8 consecutive floats W[k][n0..n0+7]   (stride-128 rows)
__device__ __forceinline__ void mm_step(const float *__restrict__ xs,
                                        const float *__restrict__ ws,
                                        unsigned long long *acc) {
    ulonglong2 a01 = *reinterpret_cast<const ulonglong2 *>(xs);
    ulonglong2 a23 = *reinterpret_cast<const ulonglong2 *>(xs + 4);
    float4 b0 = *reinterpret_cast<const float4 *>(ws);
    float4 b1 = *reinterpret_cast<const float4 *>(ws + 4);
    unsigned long long A0 = a01.x, A1 = a01.y, A2 = a23.x, A3 = a23.y;
    unsigned long long Bd[8] = {dup2(b0.x), dup2(b0.y), dup2(b0.z), dup2(b0.w),
                                dup2(b1.x), dup2(b1.y), dup2(b1.z), dup2(b1.w)};
#pragma unroll
    for (int j = 0; j < 8; j++) {
        fma2(acc[0 * 8 + j], A0, Bd[j]);
        fma2(acc[1 * 8 + j], A1, Bd[j]);
        fma2(acc[2 * 8 + j], A2, Bd[j]);
        fma2(acc[3 * 8 + j], A3, Bd[j]);
    }
}

// ---------------------------------------------------------------------------
// Kernel 1: a_self = h_self @ eW1[0:128,:] + eb1
// ---------------------------------------------------------------------------
extern __shared__ float smem[];

__global__ __launch_bounds__(256, 1) void self_kernel(
    const float *__restrict__ h_self, const float *__restrict__ eW1,
    const float *__restrict__ eb1) {
    float *sW = smem;             // 128*128 = 16384
    float *sU = sW + 16384;       // 128*132 = 16896 (union: X^T chunks / staged out)
    float *eb = sU + 16896;       // 128
    const int tid = threadIdx.x;

    for (int i = tid; i < 16384 / 4; i += 256)
        ((float4 *)sW)[i] = ((const float4 *)eW1)[i];
    if (tid < 128) eb[tid] = eb1[tid];

    const int m0 = (tid & 15) * 8;
    const int n0 = (tid >> 4) * 8;
    const int row0 = blockIdx.x * 128;
    const int lg = tid & 7, lr0 = tid >> 3;

    auto ldchunk = [&](int c, float4 *pf) {
#pragma unroll
        for (int p = 0; p < 4; p++) {
            int row = row0 + lr0 + 32 * p;
            if (row > B_ - 1) row = B_ - 1;
            pf[p] = *(const float4 *)(h_self + (size_t)row * 128 + c * 32 + lg * 4);
        }
    };
    auto stchunk = [&](float4 *pf) {
#pragma unroll
        for (int p = 0; p < 4; p++) {
            int row = lr0 + 32 * p;
            float *d = sU + (lg * 4) * 132 + row;
            d[0 * 132] = pf[p].x;
            d[1 * 132] = pf[p].y;
            d[2 * 132] = pf[p].z;
            d[3 * 132] = pf[p].w;
        }
    };

    float4 pf[4];
    ldchunk(0, pf);
    __syncthreads();
    stchunk(pf);
    __syncthreads();

    unsigned long long acc[32];
#pragma unroll
    for (int i = 0; i < 32; i++) acc[i] = 0ull;

    for (int c = 0; c < 4; c++) {
        float4 pf2[4];
        if (c < 3) ldchunk(c + 1, pf2);
        const float *xb = sU + m0;
        const float *wb = sW + c * 32 * 128 + n0;
#pragma unroll 8
        for (int kk = 0; kk < 32; kk++)
            mm_step(xb + kk * 132, wb + kk * 128, acc);
        __syncthreads();
        if (c < 3) {
            stchunk(pf2);
            __syncthreads();
        }
    }

    // stage result tile (row-major, stride 132) then coalesced write-out
#pragma unroll
    for (int j = 0; j < 8; j++) {
        float bv = eb[n0 + j];
#pragma unroll
        for (int i2 = 0; i2 < 4; i2++) {
            float2 v = unpk(acc[i2 * 8 + j]);
            sU[(m0 + 2 * i2) * 132 + n0 + j] = v.x + bv;
            sU[(m0 + 2 * i2 + 1) * 132 + n0 + j] = v.y + bv;
        }
    }
    __syncthreads();
#pragma unroll
    for (int p = 0; p < 16; p++) {
        int q = tid + 256 * p;  // float4 index (4096 total)
        int row = q >> 5;
        int c4 = (q & 31) * 4;
        int grow = row0 + row;
        if (grow < B_)
            *(float4 *)(g_aself + (size_t)grow * 128 + c4) =
                *(const float4 *)(sU + row * 132 + c4);
    }
}

// ---------------------------------------------------------------------------
// Kernel 2: edge MLP + masked reduction. Persistent; 4 nodes (128 rows) / tile.
// ---------------------------------------------------------------------------
__global__ __launch_bounds__(256, 1) void edge_kernel(
    const float *__restrict__ h_nei, const float *__restrict__ e_ij,
    const float *__restrict__ mask, const float *__restrict__ eW1,
    const float *__restrict__ eW2, const float *__restrict__ eb2, int ntiles) {
    float *sW1 = smem;                // 160*128 = 20480
    float *sW2 = sW1 + 160 * 128;     // 128*128 = 16384
    float *sU = sW2 + 16384;          // 16896 (union: X^T chunks / Y^T)
    float *mi_s = sU + 16896;         // 512
    float *mask_s = mi_s + 512;       // 128
    float *aself_s = mask_s + 128;    // 512
    float *eb2_s = aself_s + 512;     // 128
    const int tid = threadIdx.x;

    // resident weights: eW1 rows 128..287 (h_nei part + e_ij part), eW2
    for (int i = tid; i < 160 * 128 / 4; i += 256)
        ((float4 *)sW1)[i] = ((const float4 *)(eW1 + 128 * 128))[i];
    for (int i = tid; i < 16384 / 4; i += 256)
        ((float4 *)sW2)[i] = ((const float4 *)eW2)[i];
    if (tid < 128) eb2_s[tid] = eb2[tid];

    const int m0 = (tid & 15) * 8;
    const int n0 = (tid >> 4) * 8;
    const int lg = tid & 7, lr0 = tid >> 3;

    for (int tile = blockIdx.x; tile < ntiles; tile += gridDim.x) {
        const int rowbase = tile * 128;  // global neighbor-row base (= node*K + k)
        const int nb0 = tile * 4;        // first node of the tile

        if (tid < 128) mask_s[tid] = mask[(size_t)rowbase + tid];
        aself_s[tid] = g_aself[(size_t)nb0 * 128 + tid];
        aself_s[tid + 256] = g_aself[(size_t)nb0 * 128 + tid + 256];
        mi_s[tid] = 0.f;
        mi_s[tid + 256] = 0.f;

        auto ldchunk = [&](int c, float4 *pf) {
#pragma unroll
            for (int p = 0; p < 4; p++) {
                int row = lr0 + 32 * p;
                if (c < 4)
                    pf[p] = *(const float4 *)(h_nei + (size_t)(rowbase + row) * 128 +
                                              c * 32 + lg * 4);
                else
                    pf[p] = *(const float4 *)(e_ij + (size_t)(rowbase + row) * 32 +
                                              lg * 4);
            }
        };
        auto stchunk = [&](float4 *pf) {
#pragma unroll
            for (int p = 0; p < 4; p++) {
                int row = lr0 + 32 * p;
                float *d = sU + (lg * 4) * 132 + row;
                d[0 * 132] = pf[p].x;
                d[1 * 132] = pf[p].y;
                d[2 * 132] = pf[p].z;
                d[3 * 132] = pf[p].w;
            }
        };

        float4 pf[4];
        ldchunk(0, pf);
        __syncthreads();   // per-tile smem ready + previous tile fully done
        stchunk(pf);
        __syncthreads();

        unsigned long long acc[32];
#pragma unroll
        for (int i = 0; i < 32; i++) acc[i] = 0ull;

        // GEMM1: K = 160 in 5 chunks of 32 (register-prefetch next chunk)
        for (int c = 0; c < 5; c++) {
            float4 pf2[4];
            if (c < 4) ldchunk(c + 1, pf2);
            const float *xb = sU + m0;
            const float *wb = sW1 + c * 32 * 128 + n0;
#pragma unroll 8
            for (int kk = 0; kk < 32; kk++)
                mm_step(xb + kk * 132, wb + kk * 128, acc);
            __syncthreads();
            if (c < 4) {
                stchunk(pf2);
                __syncthreads();
            }
        }

        // epilogue 1: y = relu(acc + a_self[node]) -> Y^T into sU
        {
            const int g = m0 >> 5;  // node within tile (thread's 8 rows share it)
#pragma unroll
            for (int j = 0; j < 8; j++) {
                float av = aself_s[g * 128 + n0 + j];
#pragma unroll
                for (int i2 = 0; i2 < 4; i2++) {
                    float2 v = unpk(acc[i2 * 8 + j]);
                    sU[(n0 + j) * 132 + m0 + 2 * i2] = fmaxf(v.x + av, 0.f);
                    sU[(n0 + j) * 132 + m0 + 2 * i2 + 1] = fmaxf(v.y + av, 0.f);
                }
            }
        }
        __syncthreads();

        // GEMM2: K = 128 (Y^T resident)
#pragma unroll
        for (int i = 0; i < 32; i++) acc[i] = 0ull;
        {
            const float *xb = sU + m0;
            const float *wb = sW2 + n0;
#pragma unroll 8
            for (int k = 0; k < 128; k++)
                mm_step(xb + k * 132, wb + k * 128, acc);
        }

        // epilogue 2: z = relu(acc + eb2); mi[node] += mask * z
        {
            const int g = m0 >> 5;
            float mk[8];
#pragma unroll
            for (int i = 0; i < 8; i++) mk[i] = mask_s[m0 + i];
#pragma unroll
            for (int j = 0; j < 8; j++) {
                float ebv = eb2_s[n0 + j];
                float p = 0.f;
#pragma unroll
                for (int i2 = 0; i2 < 4; i2++) {
                    float2 v = unpk(acc[i2 * 8 + j]);
                    p += mk[2 * i2] * fmaxf(v.x + ebv, 0.f);
                    p += mk[2 * i2 + 1] * fmaxf(v.y + ebv, 0.f);
                }
                atomicAdd(&mi_s[g * 128 + n0 + j], p);
            }
        }
        __syncthreads();
        g_mi[(size_t)nb0 * 128 + tid] = mi_s[tid];
        g_mi[(size_t)nb0 * 128 + tid + 256] = mi_s[tid + 256];
        __syncthreads();
    }
}

// ---------------------------------------------------------------------------
// Kernel 3: node MLP.  h1 = relu([h_self|g_mi]@nW1 + nb1); out = relu(h1@nW2+nb2)
// ---------------------------------------------------------------------------
__global__ __launch_bounds__(256, 1) void node_kernel(
    const float *__restrict__ h_self, const float *__restrict__ nW1,
    const float *__restrict__ nb1, const float *__restrict__ nW2,
    const float *__restrict__ nb2, float *__restrict__ out) {
    float *sW2 = smem;            // 16384 (nW2 resident)
    float *sWc = sW2 + 16384;     // 4096  (nW1 chunk [32][128])
    float *sU = sWc + 4096;       // 16896 (union: X^T chunks / h1^T / staged out)
    float *b1s = sU + 16896;      // 128
    float *b2s = b1s + 128;       // 128
    const int tid = threadIdx.x;

    for (int i = tid; i < 16384 / 4; i += 256)
        ((float4 *)sW2)[i] = ((const float4 *)nW2)[i];
    if (tid < 128) {
        b1s[tid] = nb1[tid];
        b2s[tid] = nb2[tid];
    }

    const int m0 = (tid & 15) * 8;
    const int n0 = (tid >> 4) * 8;
    const int row0 = blockIdx.x * 128;
    const int lg = tid & 7, lr0 = tid >> 3;

    auto ldA = [&](int c, float4 *pf) {
#pragma unroll
        for (int p = 0; p < 4; p++) {
            int row = row0 + lr0 + 32 * p;
            if (row > B_ - 1) row = B_ - 1;
            const float *src = (c < 4)
                                   ? (h_self + (size_t)row * 128 + c * 32)
                                   : (g_mi + (size_t)row * 128 + (c - 4) * 32);
            pf[p] = *(const float4 *)(src + lg * 4);
        }
    };
    auto stA = [&](float4 *pf) {
#pragma unroll
        for (int p = 0; p < 4; p++) {
            int row = lr0 + 32 * p;
            float *d = sU + (lg * 4) * 132 + row;
            d[0 * 132] = pf[p].x;
            d[1 * 132] = pf[p].y;
            d[2 * 132] = pf[p].z;
            d[3 * 132] = pf[p].w;
        }
    };
    auto ldW = [&](int c, float4 *wf) {
#pragma unroll
        for (int p = 0; p < 4; p++)
            wf[p] = ((const float4 *)(nW1 + (size_t)c * 32 * 128))[tid + 256 * p];
    };
    auto stW = [&](float4 *wf) {
#pragma unroll
        for (int p = 0; p < 4; p++) ((float4 *)sWc)[tid + 256 * p] = wf[p];
    };

    float4 pa[4], pw[4];
    ldA(0, pa);
    ldW(0, pw);
    __syncthreads();
    stA(pa);
    stW(pw);
    __syncthreads();

    unsigned long long acc[32];
#pragma unroll
    for (int i = 0; i < 32; i++) acc[i] = 0ull;

    // GEMM1: K = 256 in 8 chunks (stream A and W chunks, register prefetch)
    for (int c = 0; c < 8; c++) {
        float4 pa2[4], pw2[4];
        if (c < 7) {
            ldA(c + 1, pa2);
            ldW(c + 1, pw2);
        }
        const float *xb = sU + m0;
        const float *wb = sWc + n0;
#pragma unroll 8
        for (int kk = 0; kk < 32; kk++)
            mm_step(xb + kk * 132, wb + kk * 128, acc);
        __syncthreads();
        if (c < 7) {
            stA(pa2);
            stW(pw2);
            __syncthreads();
        }
    }

    // epilogue 1: h1 = relu(acc + nb1) -> h1^T into sU
#pragma unroll
    for (int j = 0; j < 8; j++) {
        float bv = b1s[n0 + j];
#pragma unroll
        for (int i2 = 0; i2 < 4; i2++) {
            float2 v = unpk(acc[i2 * 8 + j]);
            sU[(n0 + j) * 132 + m0 + 2 * i2] = fmaxf(v.x + bv, 0.f);
            sU[(n0 + j) * 132 + m0 + 2 * i2 + 1] = fmaxf(v.y + bv, 0.f);
        }
    }
    __syncthreads();

    // GEMM2: K = 128
#pragma unroll
    for (int i = 0; i < 32; i++) acc[i] = 0ull;
    {
        const float *xb = sU + m0;
        const float *wb = sW2 + n0;
#pragma unroll 8
        for (int k = 0; k < 128; k++)
            mm_step(xb + k * 132, wb + k * 128, acc);
    }
    __syncthreads();  // done reading h1^T; reuse sU as staging

    // epilogue 2: out = relu(acc + nb2), staged then coalesced store
#pragma unroll
    for (int j = 0; j < 8; j++) {
        float bv = b2s[n0 + j];
#pragma unroll
        for (int i2 = 0; i2 < 4; i2++) {
            float2 v = unpk(acc[i2 * 8 + j]);
            sU[(m0 + 2 * i2) * 132 + n0 + j] = fmaxf(v.x + bv, 0.f);
            sU[(m0 + 2 * i2 + 1) * 132 + n0 + j] = fmaxf(v.y + bv, 0.f);
        }
    }
    __syncthreads();
#pragma unroll
    for (int p = 0; p < 16; p++) {
        int q = tid + 256 * p;
        int row = q >> 5;
        int c4 = (q & 31) * 4;
        int grow = row0 + row;
        if (grow < B_)
            *(float4 *)(out + (size_t)grow * 128 + c4) =
                *(const float4 *)(sU + row * 132 + c4);
    }
}

// ---------------------------------------------------------------------------
extern "C" void kernel_launch(void *const *d_in, const int *in_sizes, int n_in,
                              void *d_out, int out_size) {
    const float *h_self = (const float *)d_in[0];
    const float *h_nei = (const float *)d_in[1];
    const float *e_ij = (const float *)d_in[2];
    const float *mask = (const float *)d_in[3];
    const float *eW1 = (const float *)d_in[4];
    const float *eb1 = (const float *)d_in[5];
    const float *eW2 = (const float *)d_in[6];
    const float *eb2 = (const float *)d_in[7];
    const float *nW1 = (const float *)d_in[8];
    const float *nb1 = (const float *)d_in[9];
    const float *nW2 = (const float *)d_in[10];
    const float *nb2 = (const float *)d_in[11];
    float *out = (float *)d_out;

    const int SMEM_A = (16384 + 16896 + 128) * 4;
    const int SMEM_B = (20480 + 16384 + 16896 + 512 + 128 + 512 + 128) * 4;
    const int SMEM_C = (16384 + 4096 + 16896 + 256) * 4;

    cudaFuncSetAttribute(self_kernel, cudaFuncAttributeMaxDynamicSharedMemorySize,
                         SMEM_A);
    cudaFuncSetAttribute(edge_kernel, cudaFuncAttributeMaxDynamicSharedMemorySize,
                         SMEM_B);
    cudaFuncSetAttribute(node_kernel, cudaFuncAttributeMaxDynamicSharedMemorySize,
                         SMEM_C);

    int dev = 0, nsm = 148;
    cudaGetDevice(&dev);
    cudaDeviceGetAttribute(&nsm, cudaDevAttrMultiProcessorCount, dev);

    const int tilesAC = (B_ + 127) / 128;   // 391
    const int ntilesB = B_ / 4;             // 12500 (exact)

    self_kernel<<<tilesAC, 256, SMEM_A>>>(h_self, eW1, eb1);
    edge_kernel<<<nsm, 256, SMEM_B>>>(h_nei, e_ij, mask, eW1, eW2, eb2, ntilesB);
    node_kernel<<<tilesAC, 256, SMEM_C>>>(h_self, nW1, nb1, nW2, nb2, out);
}

// round 5
// speedup vs baseline: 2.2114x; 2.2114x over previous
#include <cuda_runtime.h>
#include <cuda_bf16.h>
#include <cstdint>
#include <cstddef>

// ---------------------------------------------------------------------------
// MPNN layer, fp32.  B=50000, K=32, D=128, E=32.
//  self_kernel : g_aself = h_self @ eW1[0:128] + eb1              (FFMA2)
//  edge_mma    : per 128-row tile (4 nodes x 32 neighbors), HMMA mma.sync
//                bf16 hi/lo split GEMMs (hh + hl + lh):
//                  y = relu(aself + [h_nei|e_ij] @ eW1[128:288])     K=160
//                  z = relu(y @ eW2 + eb2)                           K=128
//                  g_mi[node] = sum_k mask * z   (warp shuffle)
//  node_kernel : out = relu(relu([h_self|g_mi]@nW1+nb1)@nW2+nb2)  (FFMA2)
// ---------------------------------------------------------------------------

#define B_  50000
#define K_  32
#define D_  128
#define E_  32

__device__ float g_aself[(size_t)B_ * D_];
__device__ float g_mi[(size_t)B_ * D_];

// ======================= helpers ===========================================
__device__ __forceinline__ uint32_t smem_u32(const void* p) {
    uint32_t a;
    asm("{ .reg .u64 t; cvta.to.shared.u64 t, %1; cvt.u32.u64 %0, t; }"
        : "=r"(a) : "l"(p));
    return a;
}
// SW128-style swizzle: XOR bits[6:4] with bits[9:7] (row%8 for 128B rows)
__device__ __forceinline__ uint32_t swz(uint32_t b) { return b ^ ((b >> 3) & 0x70); }
// pack two fp32 -> bf16x2 (a in lower half)
__device__ __forceinline__ uint32_t pack2(float a, float b) {
    uint32_t r;
    asm("cvt.rn.satfinite.bf16x2.f32 %0, %1, %2;" : "=r"(r) : "f"(b), "f"(a));
    return r;
}
__device__ __forceinline__ float lo_f(uint32_t p) { return __uint_as_float(p << 16); }
__device__ __forceinline__ float hi_f(uint32_t p) { return __uint_as_float(p & 0xFFFF0000u); }

__device__ __forceinline__ void ldsm4(uint32_t* r, uint32_t addr) {
    asm volatile("ldmatrix.sync.aligned.m8n8.x4.shared.b16 {%0,%1,%2,%3}, [%4];"
                 : "=r"(r[0]), "=r"(r[1]), "=r"(r[2]), "=r"(r[3]) : "r"(addr));
}
__device__ __forceinline__ void mma16816(float* d, const uint32_t* a, const uint32_t* b) {
    asm volatile(
        "mma.sync.aligned.m16n8k16.row.col.f32.bf16.bf16.f32 "
        "{%0,%1,%2,%3}, {%4,%5,%6,%7}, {%8,%9}, {%0,%1,%2,%3};"
        : "+f"(d[0]), "+f"(d[1]), "+f"(d[2]), "+f"(d[3])
        : "r"(a[0]), "r"(a[1]), "r"(a[2]), "r"(a[3]), "r"(b[0]), "r"(b[1]));
}

// ---- packed f32x2 helpers (FFMA2 kernels) ---------------------------------
__device__ __forceinline__ unsigned long long dup2(float b) {
    unsigned long long r;
    asm("mov.b64 %0, {%1, %1};" : "=l"(r) : "f"(b));
    return r;
}
__device__ __forceinline__ void fma2(unsigned long long &d, unsigned long long a,
                                     unsigned long long b) {
    asm("fma.rn.f32x2 %0, %1, %2, %0;" : "+l"(d) : "l"(a), "l"(b));
}
__device__ __forceinline__ float2 unpk(unsigned long long v) {
    float2 r;
    asm("mov.b64 {%0, %1}, %2;" : "=f"(r.x), "=f"(r.y) : "l"(v));
    return r;
}
__device__ __forceinline__ void mm_step(const float *__restrict__ xs,
                                        const float *__restrict__ ws,
                                        unsigned long long *acc) {
    ulonglong2 a01 = *reinterpret_cast<const ulonglong2 *>(xs);
    ulonglong2 a23 = *reinterpret_cast<const ulonglong2 *>(xs + 4);
    float4 b0 = *reinterpret_cast<const float4 *>(ws);
    float4 b1 = *reinterpret_cast<const float4 *>(ws + 4);
    unsigned long long A0 = a01.x, A1 = a01.y, A2 = a23.x, A3 = a23.y;
    unsigned long long Bd[8] = {dup2(b0.x), dup2(b0.y), dup2(b0.z), dup2(b0.w),
                                dup2(b1.x), dup2(b1.y), dup2(b1.z), dup2(b1.w)};
#pragma unroll
    for (int j = 0; j < 8; j++) {
        fma2(acc[0 * 8 + j], A0, Bd[j]);
        fma2(acc[1 * 8 + j], A1, Bd[j]);
        fma2(acc[2 * 8 + j], A2, Bd[j]);
        fma2(acc[3 * 8 + j], A3, Bd[j]);
    }
}

extern __shared__ float smem[];

// ---------------------------------------------------------------------------
// Kernel 1: a_self = h_self @ eW1[0:128,:] + eb1   (FFMA2)
// ---------------------------------------------------------------------------
__global__ __launch_bounds__(256, 1) void self_kernel(
    const float *__restrict__ h_self, const float *__restrict__ eW1,
    const float *__restrict__ eb1) {
    float *sW = smem;
    float *sU = sW + 16384;
    float *eb = sU + 16896;
    const int tid = threadIdx.x;

    for (int i = tid; i < 16384 / 4; i += 256)
        ((float4 *)sW)[i] = ((const float4 *)eW1)[i];
    if (tid < 128) eb[tid] = eb1[tid];

    const int m0 = (tid & 15) * 8;
    const int n0 = (tid >> 4) * 8;
    const int row0 = blockIdx.x * 128;
    const int lg = tid & 7, lr0 = tid >> 3;

    auto ldchunk = [&](int c, float4 *pf) {
#pragma unroll
        for (int p = 0; p < 4; p++) {
            int row = row0 + lr0 + 32 * p;
            if (row > B_ - 1) row = B_ - 1;
            pf[p] = *(const float4 *)(h_self + (size_t)row * 128 + c * 32 + lg * 4);
        }
    };
    auto stchunk = [&](float4 *pf) {
#pragma unroll
        for (int p = 0; p < 4; p++) {
            int row = lr0 + 32 * p;
            float *d = sU + (lg * 4) * 132 + row;
            d[0 * 132] = pf[p].x;
            d[1 * 132] = pf[p].y;
            d[2 * 132] = pf[p].z;
            d[3 * 132] = pf[p].w;
        }
    };

    float4 pf[4];
    ldchunk(0, pf);
    __syncthreads();
    stchunk(pf);
    __syncthreads();

    unsigned long long acc[32];
#pragma unroll
    for (int i = 0; i < 32; i++) acc[i] = 0ull;

    for (int c = 0; c < 4; c++) {
        float4 pf2[4];
        if (c < 3) ldchunk(c + 1, pf2);
        const float *xb = sU + m0;
        const float *wb = sW + c * 32 * 128 + n0;
#pragma unroll 8
        for (int kk = 0; kk < 32; kk++)
            mm_step(xb + kk * 132, wb + kk * 128, acc);
        __syncthreads();
        if (c < 3) {
            stchunk(pf2);
            __syncthreads();
        }
    }
#pragma unroll
    for (int j = 0; j < 8; j++) {
        float bv = eb[n0 + j];
#pragma unroll
        for (int i2 = 0; i2 < 4; i2++) {
            float2 v = unpk(acc[i2 * 8 + j]);
            sU[(m0 + 2 * i2) * 132 + n0 + j] = v.x + bv;
            sU[(m0 + 2 * i2 + 1) * 132 + n0 + j] = v.y + bv;
        }
    }
    __syncthreads();
#pragma unroll
    for (int p = 0; p < 16; p++) {
        int q = tid + 256 * p;
        int row = q >> 5;
        int c4 = (q & 31) * 4;
        int grow = row0 + row;
        if (grow < B_)
            *(float4 *)(g_aself + (size_t)grow * 128 + c4) =
                *(const float4 *)(sU + row * 132 + c4);
    }
}

// ---------------------------------------------------------------------------
// Kernel 2: edge MLP via mma.sync bf16 hi/lo split. Persistent, 1 CTA/SM.
// SMEM layout (bytes): blocked [n/m 128][k 64] bf16, 128B rows, swizzled.
// B operands stored [n][k] => col-major k x n for mma => NON-trans ldmatrix.
// ---------------------------------------------------------------------------
#define OB1H 0        // eW1[128:288]^T hi : 3 blocks x 16384
#define OB1L 49152    // lo
#define OB2H 98304    // eW2^T hi : 2 blocks x 16384
#define OB2L 131072   // lo
#define OAY  163840   // union: A chunk (hi @+0, lo @+16384) / Y (hi 2 blk, lo @+32768)
#define EDGE_SMEM 229376

__global__ __launch_bounds__(256, 1) void edge_mma_kernel(
    const float *__restrict__ h_nei, const float *__restrict__ e_ij,
    const float *__restrict__ mask, const float *__restrict__ eW1,
    const float *__restrict__ eW2, const float *__restrict__ eb2, int ntiles) {
    char *sm = (char *)smem;
    const int tid = threadIdx.x;
    const int wid = tid >> 5, lane = tid & 31;
    const int wm = wid & 3, wn = wid >> 2;     // 4 M-groups x 2 N-groups
    const int gid = lane >> 2, tig = lane & 3;
    const uint32_t sbase = smem_u32(sm);

    // ---- one-time: weights -> bf16 hi/lo, transposed [n][k] blocked ----
    for (int idx = tid; idx < 160 * 128; idx += 256) {
        int n = idx & 127, k = idx >> 7;
        int c = k >> 6, kk = k & 63;
        float w = eW1[(size_t)(128 + k) * 128 + n];
        uint32_t p = pack2(w, 0.f);
        uint32_t q = pack2(w - lo_f(p), 0.f);
        uint32_t off = c * 16384 + swz(n * 128 + kk * 2);
        *(uint16_t *)(sm + OB1H + off) = (uint16_t)p;
        *(uint16_t *)(sm + OB1L + off) = (uint16_t)q;
    }
    for (int idx = tid; idx < 128 * 128; idx += 256) {
        int n = idx & 127, k = idx >> 7;
        int c = k >> 6, kk = k & 63;
        float w = eW2[(size_t)k * 128 + n];
        uint32_t p = pack2(w, 0.f);
        uint32_t q = pack2(w - lo_f(p), 0.f);
        uint32_t off = c * 16384 + swz(n * 128 + kk * 2);
        *(uint16_t *)(sm + OB2H + off) = (uint16_t)p;
        *(uint16_t *)(sm + OB2L + off) = (uint16_t)q;
    }

    // per-thread ldmatrix lane-address components
    const int arow = lane & 15;                 // A: rows m0..m0+15
    const int ak = (lane >> 4) * 8;             // A: k-half
    const int brow = (lane & 7) + 8 * (lane >> 4);  // B: n rows (matrix pairs)
    const int bk = 8 * ((lane >> 3) & 1);       // B: k-half

    __syncthreads();

    for (int tile = blockIdx.x; tile < ntiles; tile += gridDim.x) {
        const size_t rowbase = (size_t)tile * 128;
        const int nb0 = tile * 4;

        float acc[2][8][4];
#pragma unroll
        for (int m = 0; m < 2; m++)
#pragma unroll
            for (int nt = 0; nt < 8; nt++)
#pragma unroll
                for (int j = 0; j < 4; j++) acc[m][nt][j] = 0.f;

        // prefetch chunk 0 (h_nei k0-63)
        float4 pf[8];
#pragma unroll
        for (int i = 0; i < 8; i++) {
            int q = tid + 256 * i;
            pf[i] = *(const float4 *)(h_nei + (rowbase + (q >> 4)) * 128 + (q & 15) * 4);
        }

        // ---- GEMM1: K=160 in chunks {64,64,32} ----
        for (int c = 0; c < 3; c++) {
            __syncthreads();  // A buffer free (prev chunk MMA / prev tile done)
            if (c < 2) {
#pragma unroll
                for (int i = 0; i < 8; i++) {
                    int q = tid + 256 * i;
                    int r = q >> 4, kc = (q & 15) * 4;
                    uint32_t off = swz((uint32_t)(r * 128 + kc * 2));
                    uint32_t h01 = pack2(pf[i].x, pf[i].y), h23 = pack2(pf[i].z, pf[i].w);
                    uint32_t l01 = pack2(pf[i].x - lo_f(h01), pf[i].y - hi_f(h01));
                    uint32_t l23 = pack2(pf[i].z - lo_f(h23), pf[i].w - hi_f(h23));
                    *(uint2 *)(sm + OAY + off) = make_uint2(h01, h23);
                    *(uint2 *)(sm + OAY + 16384 + off) = make_uint2(l01, l23);
                }
            } else {
#pragma unroll
                for (int i = 0; i < 4; i++) {
                    int q = tid + 256 * i;
                    int r = q >> 3, kc = (q & 7) * 4;
                    uint32_t off = swz((uint32_t)(r * 128 + kc * 2));
                    uint32_t h01 = pack2(pf[i].x, pf[i].y), h23 = pack2(pf[i].z, pf[i].w);
                    uint32_t l01 = pack2(pf[i].x - lo_f(h01), pf[i].y - hi_f(h01));
                    uint32_t l23 = pack2(pf[i].z - lo_f(h23), pf[i].w - hi_f(h23));
                    *(uint2 *)(sm + OAY + off) = make_uint2(h01, h23);
                    *(uint2 *)(sm + OAY + 16384 + off) = make_uint2(l01, l23);
                }
            }
            __syncthreads();
            // prefetch next chunk (overlaps MMA)
            if (c == 0) {
#pragma unroll
                for (int i = 0; i < 8; i++) {
                    int q = tid + 256 * i;
                    pf[i] = *(const float4 *)(h_nei + (rowbase + (q >> 4)) * 128 + 64 +
                                              (q & 15) * 4);
                }
            } else if (c == 1) {
#pragma unroll
                for (int i = 0; i < 4; i++) {
                    int q = tid + 256 * i;
                    pf[i] = *(const float4 *)(e_ij + (rowbase + (q >> 3)) * 32 + (q & 7) * 4);
                }
            }
            const int nk = (c == 2) ? 2 : 4;
            const uint32_t bh_base = sbase + OB1H + c * 16384;
            const uint32_t bl_base = sbase + OB1L + c * 16384;
            for (int ks = 0; ks < nk; ks++) {
                uint32_t ah[2][4], al[2][4];
#pragma unroll
                for (int m = 0; m < 2; m++) {
                    uint32_t off =
                        swz((uint32_t)((32 * wm + 16 * m + arow) * 128 + (ks * 16 + ak) * 2));
                    ldsm4(ah[m], sbase + OAY + off);
                    ldsm4(al[m], sbase + OAY + 16384 + off);
                }
                uint32_t bh[4][4], bl[4][4];
#pragma unroll
                for (int p = 0; p < 4; p++) {
                    uint32_t off =
                        swz((uint32_t)((64 * wn + 16 * p + brow) * 128 + (ks * 16 + bk) * 2));
                    ldsm4(bh[p], bh_base + off);
                    ldsm4(bl[p], bl_base + off);
                }
#pragma unroll
                for (int m = 0; m < 2; m++)
#pragma unroll
                    for (int p = 0; p < 4; p++) {
                        mma16816(acc[m][2 * p], ah[m], &bh[p][0]);
                        mma16816(acc[m][2 * p + 1], ah[m], &bh[p][2]);
                        mma16816(acc[m][2 * p], ah[m], &bl[p][0]);
                        mma16816(acc[m][2 * p + 1], ah[m], &bl[p][2]);
                        mma16816(acc[m][2 * p], al[m], &bh[p][0]);
                        mma16816(acc[m][2 * p + 1], al[m], &bh[p][2]);
                    }
            }
        }
        __syncthreads();  // all GEMM1 reads of A buffer done

        // ---- epilogue 1: y = relu(acc + aself) -> Y (bf16 hi/lo, blocked) ----
#pragma unroll
        for (int nt = 0; nt < 8; nt++) {
            int c0 = 64 * wn + 8 * nt + 2 * tig;
            float as0 = g_aself[(size_t)(nb0 + wm) * 128 + c0];
            float as1 = g_aself[(size_t)(nb0 + wm) * 128 + c0 + 1];
            int cblk = c0 >> 6, ckk = c0 & 63;
#pragma unroll
            for (int m = 0; m < 2; m++) {
                int r = 32 * wm + 16 * m + gid;
                float y00 = fmaxf(acc[m][nt][0] + as0, 0.f);
                float y01 = fmaxf(acc[m][nt][1] + as1, 0.f);
                float y10 = fmaxf(acc[m][nt][2] + as0, 0.f);
                float y11 = fmaxf(acc[m][nt][3] + as1, 0.f);
                uint32_t off0 = cblk * 16384 + swz((uint32_t)(r * 128 + ckk * 2));
                uint32_t off1 = cblk * 16384 + swz((uint32_t)((r + 8) * 128 + ckk * 2));
                uint32_t h0 = pack2(y00, y01);
                uint32_t h1 = pack2(y10, y11);
                *(uint32_t *)(sm + OAY + off0) = h0;
                *(uint32_t *)(sm + OAY + off1) = h1;
                *(uint32_t *)(sm + OAY + 32768 + off0) =
                    pack2(y00 - lo_f(h0), y01 - hi_f(h0));
                *(uint32_t *)(sm + OAY + 32768 + off1) =
                    pack2(y10 - lo_f(h1), y11 - hi_f(h1));
            }
        }
        __syncthreads();

        // ---- GEMM2: K=128, A = y (SMEM), B = eW2 ----
#pragma unroll
        for (int m = 0; m < 2; m++)
#pragma unroll
            for (int nt = 0; nt < 8; nt++)
#pragma unroll
                for (int j = 0; j < 4; j++) acc[m][nt][j] = 0.f;

        for (int ks = 0; ks < 8; ks++) {
            int cblk = ks >> 2, kks = ks & 3;
            uint32_t ah[2][4], al[2][4];
#pragma unroll
            for (int m = 0; m < 2; m++) {
                uint32_t off = cblk * 16384 +
                    swz((uint32_t)((32 * wm + 16 * m + arow) * 128 + (kks * 16 + ak) * 2));
                ldsm4(ah[m], sbase + OAY + off);
                ldsm4(al[m], sbase + OAY + 32768 + off);
            }
            uint32_t bh[4][4], bl[4][4];
#pragma unroll
            for (int p = 0; p < 4; p++) {
                uint32_t off = cblk * 16384 +
                    swz((uint32_t)((64 * wn + 16 * p + brow) * 128 + (kks * 16 + bk) * 2));
                ldsm4(bh[p], sbase + OB2H + off);
                ldsm4(bl[p], sbase + OB2L + off);
            }
#pragma unroll
            for (int m = 0; m < 2; m++)
#pragma unroll
                for (int p = 0; p < 4; p++) {
                    mma16816(acc[m][2 * p], ah[m], &bh[p][0]);
                    mma16816(acc[m][2 * p + 1], ah[m], &bh[p][2]);
                    mma16816(acc[m][2 * p], ah[m], &bl[p][0]);
                    mma16816(acc[m][2 * p + 1], ah[m], &bl[p][2]);
                    mma16816(acc[m][2 * p], al[m], &bh[p][0]);
                    mma16816(acc[m][2 * p + 1], al[m], &bh[p][2]);
                }
        }
        __syncthreads();  // Y reads done (next tile overwrites)

        // ---- epilogue 2: z = relu(acc+eb2); g_mi[node] = sum_k mask*z ----
        {
            float mk[2][2];
#pragma unroll
            for (int m = 0; m < 2; m++) {
                mk[m][0] = mask[rowbase + 32 * wm + 16 * m + gid];
                mk[m][1] = mask[rowbase + 32 * wm + 16 * m + gid + 8];
            }
#pragma unroll
            for (int nt = 0; nt < 8; nt++) {
                int c0 = 64 * wn + 8 * nt + 2 * tig;
                float eb0 = eb2[c0], eb1v = eb2[c0 + 1];
                float s0 = 0.f, s1 = 0.f;
#pragma unroll
                for (int m = 0; m < 2; m++) {
                    s0 += mk[m][0] * fmaxf(acc[m][nt][0] + eb0, 0.f) +
                          mk[m][1] * fmaxf(acc[m][nt][2] + eb0, 0.f);
                    s1 += mk[m][0] * fmaxf(acc[m][nt][1] + eb1v, 0.f) +
                          mk[m][1] * fmaxf(acc[m][nt][3] + eb1v, 0.f);
                }
#pragma unroll
                for (int o = 4; o <= 16; o <<= 1) {
                    s0 += __shfl_xor_sync(0xffffffffu, s0, o);
                    s1 += __shfl_xor_sync(0xffffffffu, s1, o);
                }
                if (lane < 4) {
                    g_mi[(size_t)(nb0 + wm) * 128 + c0] = s0;
                    g_mi[(size_t)(nb0 + wm) * 128 + c0 + 1] = s1;
                }
            }
        }
    }
}

// ---------------------------------------------------------------------------
// Kernel 3: node MLP (FFMA2)
// ---------------------------------------------------------------------------
__global__ __launch_bounds__(256, 1) void node_kernel(
    const float *__restrict__ h_self, const float *__restrict__ nW1,
    const float *__restrict__ nb1, const float *__restrict__ nW2,
    const float *__restrict__ nb2, float *__restrict__ out) {
    float *sW2 = smem;
    float *sWc = sW2 + 16384;
    float *sU = sWc + 4096;
    float *b1s = sU + 16896;
    float *b2s = b1s + 128;
    const int tid = threadIdx.x;

    for (int i = tid; i < 16384 / 4; i += 256)
        ((float4 *)sW2)[i] = ((const float4 *)nW2)[i];
    if (tid < 128) {
        b1s[tid] = nb1[tid];
        b2s[tid] = nb2[tid];
    }

    const int m0 = (tid & 15) * 8;
    const int n0 = (tid >> 4) * 8;
    const int row0 = blockIdx.x * 128;
    const int lg = tid & 7, lr0 = tid >> 3;

    auto ldA = [&](int c, float4 *pf) {
#pragma unroll
        for (int p = 0; p < 4; p++) {
            int row = row0 + lr0 + 32 * p;
            if (row > B_ - 1) row = B_ - 1;
            const float *src = (c < 4) ? (h_self + (size_t)row * 128 + c * 32)
                                       : (g_mi + (size_t)row * 128 + (c - 4) * 32);
            pf[p] = *(const float4 *)(src + lg * 4);
        }
    };
    auto stA = [&](float4 *pf) {
#pragma unroll
        for (int p = 0; p < 4; p++) {
            int row = lr0 + 32 * p;
            float *d = sU + (lg * 4) * 132 + row;
            d[0 * 132] = pf[p].x;
            d[1 * 132] = pf[p].y;
            d[2 * 132] = pf[p].z;
            d[3 * 132] = pf[p].w;
        }
    };
    auto ldW = [&](int c, float4 *wf) {
#pragma unroll
        for (int p = 0; p < 4; p++)
            wf[p] = ((const float4 *)(nW1 + (size_t)c * 32 * 128))[tid + 256 * p];
    };
    auto stW = [&](float4 *wf) {
#pragma unroll
        for (int p = 0; p < 4; p++) ((float4 *)sWc)[tid + 256 * p] = wf[p];
    };

    float4 pa[4], pw[4];
    ldA(0, pa);
    ldW(0, pw);
    __syncthreads();
    stA(pa);
    stW(pw);
    __syncthreads();

    unsigned long long acc[32];
#pragma unroll
    for (int i = 0; i < 32; i++) acc[i] = 0ull;

    for (int c = 0; c < 8; c++) {
        float4 pa2[4], pw2[4];
        if (c < 7) {
            ldA(c + 1, pa2);
            ldW(c + 1, pw2);
        }
        const float *xb = sU + m0;
        const float *wb = sWc + n0;
#pragma unroll 8
        for (int kk = 0; kk < 32; kk++)
            mm_step(xb + kk * 132, wb + kk * 128, acc);
        __syncthreads();
        if (c < 7) {
            stA(pa2);
            stW(pw2);
            __syncthreads();
        }
    }
#pragma unroll
    for (int j = 0; j < 8; j++) {
        float bv = b1s[n0 + j];
#pragma unroll
        for (int i2 = 0; i2 < 4; i2++) {
            float2 v = unpk(acc[i2 * 8 + j]);
            sU[(n0 + j) * 132 + m0 + 2 * i2] = fmaxf(v.x + bv, 0.f);
            sU[(n0 + j) * 132 + m0 + 2 * i2 + 1] = fmaxf(v.y + bv, 0.f);
        }
    }
    __syncthreads();
#pragma unroll
    for (int i = 0; i < 32; i++) acc[i] = 0ull;
    {
        const float *xb = sU + m0;
        const float *wb = sW2 + n0;
#pragma unroll 8
        for (int k = 0; k < 128; k++)
            mm_step(xb + k * 132, wb + k * 128, acc);
    }
    __syncthreads();
#pragma unroll
    for (int j = 0; j < 8; j++) {
        float bv = b2s[n0 + j];
#pragma unroll
        for (int i2 = 0; i2 < 4; i2++) {
            float2 v = unpk(acc[i2 * 8 + j]);
            sU[(m0 + 2 * i2) * 132 + n0 + j] = fmaxf(v.x + bv, 0.f);
            sU[(m0 + 2 * i2 + 1) * 132 + n0 + j] = fmaxf(v.y + bv, 0.f);
        }
    }
    __syncthreads();
#pragma unroll
    for (int p = 0; p < 16; p++) {
        int q = tid + 256 * p;
        int row = q >> 5;
        int c4 = (q & 31) * 4;
        int grow = row0 + row;
        if (grow < B_)
            *(float4 *)(out + (size_t)grow * 128 + c4) =
                *(const float4 *)(sU + row * 132 + c4);
    }
}

// ---------------------------------------------------------------------------
extern "C" void kernel_launch(void *const *d_in, const int *in_sizes, int n_in,
                              void *d_out, int out_size) {
    const float *h_self = (const float *)d_in[0];
    const float *h_nei = (const float *)d_in[1];
    const float *e_ij = (const float *)d_in[2];
    const float *mask = (const float *)d_in[3];
    const float *eW1 = (const float *)d_in[4];
    const float *eb1 = (const float *)d_in[5];
    const float *eW2 = (const float *)d_in[6];
    const float *eb2 = (const float *)d_in[7];
    const float *nW1 = (const float *)d_in[8];
    const float *nb1 = (const float *)d_in[9];
    const float *nW2 = (const float *)d_in[10];
    const float *nb2 = (const float *)d_in[11];
    float *out = (float *)d_out;

    const int SMEM_A = (16384 + 16896 + 128) * 4;
    const int SMEM_C = (16384 + 4096 + 16896 + 256) * 4;

    cudaFuncSetAttribute(self_kernel, cudaFuncAttributeMaxDynamicSharedMemorySize,
                         SMEM_A);
    cudaFuncSetAttribute(edge_mma_kernel,
                         cudaFuncAttributeMaxDynamicSharedMemorySize, EDGE_SMEM);
    cudaFuncSetAttribute(node_kernel, cudaFuncAttributeMaxDynamicSharedMemorySize,
                         SMEM_C);

    int dev = 0, nsm = 148;
    cudaGetDevice(&dev);
    cudaDeviceGetAttribute(&nsm, cudaDevAttrMultiProcessorCount, dev);

    const int tilesAC = (B_ + 127) / 128;  // 391
    const int ntilesB = B_ / 4;            // 12500

    self_kernel<<<tilesAC, 256, SMEM_A>>>(h_self, eW1, eb1);
    edge_mma_kernel<<<nsm, 256, EDGE_SMEM>>>(h_nei, e_ij, mask, eW1, eW2, eb2,
                                             ntilesB);
    node_kernel<<<tilesAC, 256, SMEM_C>>>(h_self, nW1, nb1, nW2, nb2, out);
}

// round 6
// speedup vs baseline: 2.4273x; 1.0976x over previous
#include <cuda_runtime.h>
#include <cuda_bf16.h>
#include <cstdint>
#include <cstddef>

// ---------------------------------------------------------------------------
// MPNN layer, fp32.  B=50000, K=32, D=128, E=32.
//  self_kernel : g_aself = h_self @ eW1[0:128] + eb1              (FFMA2)
//  edge_mma    : per 128-row tile (4 nodes x 32 neighbors), HMMA mma.sync
//                bf16 hi/lo split GEMMs (hh + hl + lh), software-pipelined
//                fragment loads:
//                  y = relu(aself + [h_nei|e_ij] @ eW1[128:288])     K=160
//                  z = relu(y @ eW2 + eb2)                           K=128
//                  g_mi[node] = sum_k mask * z   (warp shuffle)
//  node_kernel : out = relu(relu([h_self|g_mi]@nW1+nb1)@nW2+nb2)  (FFMA2)
// ---------------------------------------------------------------------------

#define B_  50000
#define K_  32
#define D_  128
#define E_  32

__device__ float g_aself[(size_t)B_ * D_];
__device__ float g_mi[(size_t)B_ * D_];

// ======================= helpers ===========================================
__device__ __forceinline__ uint32_t smem_u32(const void* p) {
    uint32_t a;
    asm("{ .reg .u64 t; cvta.to.shared.u64 t, %1; cvt.u32.u64 %0, t; }"
        : "=r"(a) : "l"(p));
    return a;
}
// SW128-style swizzle: XOR bits[6:4] with bits[9:7]
__device__ __forceinline__ uint32_t swz(uint32_t b) { return b ^ ((b >> 3) & 0x70); }
// pack two fp32 -> bf16x2 (a in lower half)
__device__ __forceinline__ uint32_t pack2(float a, float b) {
    uint32_t r;
    asm("cvt.rn.satfinite.bf16x2.f32 %0, %1, %2;" : "=r"(r) : "f"(b), "f"(a));
    return r;
}
__device__ __forceinline__ float lo_f(uint32_t p) { return __uint_as_float(p << 16); }
__device__ __forceinline__ float hi_f(uint32_t p) { return __uint_as_float(p & 0xFFFF0000u); }

__device__ __forceinline__ void ldsm4(uint32_t* r, uint32_t addr) {
    asm volatile("ldmatrix.sync.aligned.m8n8.x4.shared.b16 {%0,%1,%2,%3}, [%4];"
                 : "=r"(r[0]), "=r"(r[1]), "=r"(r[2]), "=r"(r[3]) : "r"(addr));
}
// NON-volatile: pure register computation, let the compiler schedule freely.
__device__ __forceinline__ void mma16816(float* d, const uint32_t* a, const uint32_t* b) {
    asm("mma.sync.aligned.m16n8k16.row.col.f32.bf16.bf16.f32 "
        "{%0,%1,%2,%3}, {%4,%5,%6,%7}, {%8,%9}, {%0,%1,%2,%3};"
        : "+f"(d[0]), "+f"(d[1]), "+f"(d[2]), "+f"(d[3])
        : "r"(a[0]), "r"(a[1]), "r"(a[2]), "r"(a[3]), "r"(b[0]), "r"(b[1]));
}

// ---- packed f32x2 helpers (FFMA2 kernels) ---------------------------------
__device__ __forceinline__ unsigned long long dup2(float b) {
    unsigned long long r;
    asm("mov.b64 %0, {%1, %1};" : "=l"(r) : "f"(b));
    return r;
}
__device__ __forceinline__ void fma2(unsigned long long &d, unsigned long long a,
                                     unsigned long long b) {
    asm("fma.rn.f32x2 %0, %1, %2, %0;" : "+l"(d) : "l"(a), "l"(b));
}
__device__ __forceinline__ float2 unpk(unsigned long long v) {
    float2 r;
    asm("mov.b64 {%0, %1}, %2;" : "=f"(r.x), "=f"(r.y) : "l"(v));
    return r;
}
__device__ __forceinline__ void mm_step(const float *__restrict__ xs,
                                        const float *__restrict__ ws,
                                        unsigned long long *acc) {
    ulonglong2 a01 = *reinterpret_cast<const ulonglong2 *>(xs);
    ulonglong2 a23 = *reinterpret_cast<const ulonglong2 *>(xs + 4);
    float4 b0 = *reinterpret_cast<const float4 *>(ws);
    float4 b1 = *reinterpret_cast<const float4 *>(ws + 4);
    unsigned long long A0 = a01.x, A1 = a01.y, A2 = a23.x, A3 = a23.y;
    unsigned long long Bd[8] = {dup2(b0.x), dup2(b0.y), dup2(b0.z), dup2(b0.w),
                                dup2(b1.x), dup2(b1.y), dup2(b1.z), dup2(b1.w)};
#pragma unroll
    for (int j = 0; j < 8; j++) {
        fma2(acc[0 * 8 + j], A0, Bd[j]);
        fma2(acc[1 * 8 + j], A1, Bd[j]);
        fma2(acc[2 * 8 + j], A2, Bd[j]);
        fma2(acc[3 * 8 + j], A3, Bd[j]);
    }
}

extern __shared__ float smem[];

// ---------------------------------------------------------------------------
// Kernel 1: a_self = h_self @ eW1[0:128,:] + eb1   (FFMA2)
// ---------------------------------------------------------------------------
__global__ __launch_bounds__(256, 1) void self_kernel(
    const float *__restrict__ h_self, const float *__restrict__ eW1,
    const float *__restrict__ eb1) {
    float *sW = smem;
    float *sU = sW + 16384;
    float *eb = sU + 16896;
    const int tid = threadIdx.x;

    for (int i = tid; i < 16384 / 4; i += 256)
        ((float4 *)sW)[i] = ((const float4 *)eW1)[i];
    if (tid < 128) eb[tid] = eb1[tid];

    const int m0 = (tid & 15) * 8;
    const int n0 = (tid >> 4) * 8;
    const int row0 = blockIdx.x * 128;
    const int lg = tid & 7, lr0 = tid >> 3;

    auto ldchunk = [&](int c, float4 *pf) {
#pragma unroll
        for (int p = 0; p < 4; p++) {
            int row = row0 + lr0 + 32 * p;
            if (row > B_ - 1) row = B_ - 1;
            pf[p] = *(const float4 *)(h_self + (size_t)row * 128 + c * 32 + lg * 4);
        }
    };
    auto stchunk = [&](float4 *pf) {
#pragma unroll
        for (int p = 0; p < 4; p++) {
            int row = lr0 + 32 * p;
            float *d = sU + (lg * 4) * 132 + row;
            d[0 * 132] = pf[p].x;
            d[1 * 132] = pf[p].y;
            d[2 * 132] = pf[p].z;
            d[3 * 132] = pf[p].w;
        }
    };

    float4 pf[4];
    ldchunk(0, pf);
    __syncthreads();
    stchunk(pf);
    __syncthreads();

    unsigned long long acc[32];
#pragma unroll
    for (int i = 0; i < 32; i++) acc[i] = 0ull;

    for (int c = 0; c < 4; c++) {
        float4 pf2[4];
        if (c < 3) ldchunk(c + 1, pf2);
        const float *xb = sU + m0;
        const float *wb = sW + c * 32 * 128 + n0;
#pragma unroll 8
        for (int kk = 0; kk < 32; kk++)
            mm_step(xb + kk * 132, wb + kk * 128, acc);
        __syncthreads();
        if (c < 3) {
            stchunk(pf2);
            __syncthreads();
        }
    }
#pragma unroll
    for (int j = 0; j < 8; j++) {
        float bv = eb[n0 + j];
#pragma unroll
        for (int i2 = 0; i2 < 4; i2++) {
            float2 v = unpk(acc[i2 * 8 + j]);
            sU[(m0 + 2 * i2) * 132 + n0 + j] = v.x + bv;
            sU[(m0 + 2 * i2 + 1) * 132 + n0 + j] = v.y + bv;
        }
    }
    __syncthreads();
#pragma unroll
    for (int p = 0; p < 16; p++) {
        int q = tid + 256 * p;
        int row = q >> 5;
        int c4 = (q & 31) * 4;
        int grow = row0 + row;
        if (grow < B_)
            *(float4 *)(g_aself + (size_t)grow * 128 + c4) =
                *(const float4 *)(sU + row * 132 + c4);
    }
}

// ---------------------------------------------------------------------------
// Kernel 2: edge MLP via mma.sync bf16 hi/lo split, pipelined fragments.
// SMEM layout (bytes): blocked [n/m 128][k 64] bf16, 128B rows, swizzled.
// ---------------------------------------------------------------------------
#define OB1H 0        // eW1[128:288]^T hi : 3 blocks x 16384
#define OB1L 49152    // lo
#define OB2H 98304    // eW2^T hi : 2 blocks x 16384
#define OB2L 131072   // lo
#define OAY  163840   // union: A chunk (hi @+0, lo @+16384) / Y (hi 2 blk, lo @+32768)
#define OASELF 229376 // 512 floats (2048 B)
#define OMASK  231424 // 128 floats (512 B)
#define EDGE_SMEM 231936

__global__ __launch_bounds__(256, 1) void edge_mma_kernel(
    const float *__restrict__ h_nei, const float *__restrict__ e_ij,
    const float *__restrict__ mask, const float *__restrict__ eW1,
    const float *__restrict__ eW2, const float *__restrict__ eb2, int ntiles) {
    char *sm = (char *)smem;
    float *aself_s = (float *)(sm + OASELF);
    float *mask_s = (float *)(sm + OMASK);
    const int tid = threadIdx.x;
    const int wid = tid >> 5, lane = tid & 31;
    const int wm = wid & 3, wn = wid >> 2;     // 4 M-groups x 2 N-groups
    const int gid = lane >> 2, tig = lane & 3;
    const uint32_t sbase = smem_u32(sm);

    // ---- one-time: weights -> bf16 hi/lo, transposed [n][k] blocked ----
    for (int idx = tid; idx < 160 * 128; idx += 256) {
        int n = idx & 127, k = idx >> 7;
        int c = k >> 6, kk = k & 63;
        float w = eW1[(size_t)(128 + k) * 128 + n];
        uint32_t p = pack2(w, 0.f);
        uint32_t q = pack2(w - lo_f(p), 0.f);
        uint32_t off = c * 16384 + swz(n * 128 + kk * 2);
        *(uint16_t *)(sm + OB1H + off) = (uint16_t)p;
        *(uint16_t *)(sm + OB1L + off) = (uint16_t)q;
    }
    for (int idx = tid; idx < 128 * 128; idx += 256) {
        int n = idx & 127, k = idx >> 7;
        int c = k >> 6, kk = k & 63;
        float w = eW2[(size_t)k * 128 + n];
        uint32_t p = pack2(w, 0.f);
        uint32_t q = pack2(w - lo_f(p), 0.f);
        uint32_t off = c * 16384 + swz(n * 128 + kk * 2);
        *(uint16_t *)(sm + OB2H + off) = (uint16_t)p;
        *(uint16_t *)(sm + OB2L + off) = (uint16_t)q;
    }

    // per-thread ldmatrix lane-address components
    const int arow = lane & 15;                 // A: rows m0..m0+15
    const int ak = (lane >> 4) * 8;             // A: k-half
    const int brow = (lane & 7) + 8 * (lane >> 4);  // B: n rows
    const int bk = 8 * ((lane >> 3) & 1);       // B: k-half

    // fragment double buffers
    uint32_t AH[2][2][4], AL[2][2][4], BH[2][4][4], BL[2][4][4];

    auto ldA = [&](uint32_t baseH, uint32_t baseL, int koff,
                   uint32_t (&AHb)[2][4], uint32_t (&ALb)[2][4]) {
#pragma unroll
        for (int m = 0; m < 2; m++) {
            uint32_t off = swz((uint32_t)((32 * wm + 16 * m + arow) * 128 + koff * 2));
            ldsm4(AHb[m], baseH + off);
            ldsm4(ALb[m], baseL + off);
        }
    };
    auto ldB = [&](uint32_t baseH, uint32_t baseL, int koff,
                   uint32_t (&BHb)[4][4], uint32_t (&BLb)[4][4]) {
#pragma unroll
        for (int p = 0; p < 4; p++) {
            uint32_t off = swz((uint32_t)((64 * wn + 16 * p + brow) * 128 + koff * 2));
            ldsm4(BHb[p], baseH + off);
            ldsm4(BLb[p], baseL + off);
        }
    };

    __syncthreads();

    for (int tile = blockIdx.x; tile < ntiles; tile += gridDim.x) {
        const size_t rowbase = (size_t)tile * 128;
        const int nb0 = tile * 4;

        __syncthreads();  // prev tile fully done with mask_s/aself_s/OAY
        if (tid < 128) mask_s[tid] = mask[rowbase + tid];
        aself_s[tid] = g_aself[(size_t)nb0 * 128 + tid];
        aself_s[tid + 256] = g_aself[(size_t)nb0 * 128 + tid + 256];

        float acc[2][8][4];
#pragma unroll
        for (int m = 0; m < 2; m++)
#pragma unroll
            for (int nt = 0; nt < 8; nt++)
#pragma unroll
                for (int j = 0; j < 4; j++) acc[m][nt][j] = 0.f;

        // prefetch chunk 0 (h_nei k0-63)
        float4 pf[8];
#pragma unroll
        for (int i = 0; i < 8; i++) {
            int q = tid + 256 * i;
            pf[i] = *(const float4 *)(h_nei + (rowbase + (q >> 4)) * 128 + (q & 15) * 4);
        }

        // ---- GEMM1: K=160 in chunks {64,64,32}, pipelined fragments ----
#pragma unroll
        for (int c = 0; c < 3; c++) {
            __syncthreads();  // A buffer free
            if (c < 2) {
#pragma unroll
                for (int i = 0; i < 8; i++) {
                    int q = tid + 256 * i;
                    int r = q >> 4, kc = (q & 15) * 4;
                    uint32_t off = swz((uint32_t)(r * 128 + kc * 2));
                    uint32_t h01 = pack2(pf[i].x, pf[i].y), h23 = pack2(pf[i].z, pf[i].w);
                    uint32_t l01 = pack2(pf[i].x - lo_f(h01), pf[i].y - hi_f(h01));
                    uint32_t l23 = pack2(pf[i].z - lo_f(h23), pf[i].w - hi_f(h23));
                    *(uint2 *)(sm + OAY + off) = make_uint2(h01, h23);
                    *(uint2 *)(sm + OAY + 16384 + off) = make_uint2(l01, l23);
                }
            } else {
#pragma unroll
                for (int i = 0; i < 4; i++) {
                    int q = tid + 256 * i;
                    int r = q >> 3, kc = (q & 7) * 4;
                    uint32_t off = swz((uint32_t)(r * 128 + kc * 2));
                    uint32_t h01 = pack2(pf[i].x, pf[i].y), h23 = pack2(pf[i].z, pf[i].w);
                    uint32_t l01 = pack2(pf[i].x - lo_f(h01), pf[i].y - hi_f(h01));
                    uint32_t l23 = pack2(pf[i].z - lo_f(h23), pf[i].w - hi_f(h23));
                    *(uint2 *)(sm + OAY + off) = make_uint2(h01, h23);
                    *(uint2 *)(sm + OAY + 16384 + off) = make_uint2(l01, l23);
                }
            }
            __syncthreads();  // A ready
            // prefetch next chunk's global data (overlaps MMA)
            if (c == 0) {
#pragma unroll
                for (int i = 0; i < 8; i++) {
                    int q = tid + 256 * i;
                    pf[i] = *(const float4 *)(h_nei + (rowbase + (q >> 4)) * 128 + 64 +
                                              (q & 15) * 4);
                }
            } else if (c == 1) {
#pragma unroll
                for (int i = 0; i < 4; i++) {
                    int q = tid + 256 * i;
                    pf[i] = *(const float4 *)(e_ij + (rowbase + (q >> 3)) * 32 + (q & 7) * 4);
                }
            }
            const int nk = (c == 2) ? 2 : 4;
            const uint32_t aHb = sbase + OAY, aLb = sbase + OAY + 16384;
            const uint32_t bHb = sbase + OB1H + c * 16384;
            const uint32_t bLb = sbase + OB1L + c * 16384;
            ldA(aHb, aLb, ak, AH[0], AL[0]);
            ldB(bHb, bLb, bk, BH[0], BL[0]);
#pragma unroll
            for (int ks = 0; ks < 4; ks++) {
                if (ks < nk) {
                    const int cur = ks & 1, nxt = cur ^ 1;
                    if (ks + 1 < nk) {
                        ldA(aHb, aLb, (ks + 1) * 16 + ak, AH[nxt], AL[nxt]);
                        ldB(bHb, bLb, (ks + 1) * 16 + bk, BH[nxt], BL[nxt]);
                    }
                    // hh (16 independent)
#pragma unroll
                    for (int m = 0; m < 2; m++)
#pragma unroll
                        for (int p = 0; p < 4; p++) {
                            mma16816(acc[m][2 * p], AH[cur][m], &BH[cur][p][0]);
                            mma16816(acc[m][2 * p + 1], AH[cur][m], &BH[cur][p][2]);
                        }
                    // hl
#pragma unroll
                    for (int m = 0; m < 2; m++)
#pragma unroll
                        for (int p = 0; p < 4; p++) {
                            mma16816(acc[m][2 * p], AH[cur][m], &BL[cur][p][0]);
                            mma16816(acc[m][2 * p + 1], AH[cur][m], &BL[cur][p][2]);
                        }
                    // lh
#pragma unroll
                    for (int m = 0; m < 2; m++)
#pragma unroll
                        for (int p = 0; p < 4; p++) {
                            mma16816(acc[m][2 * p], AL[cur][m], &BH[cur][p][0]);
                            mma16816(acc[m][2 * p + 1], AL[cur][m], &BH[cur][p][2]);
                        }
                }
            }
        }
        __syncthreads();  // all GEMM1 reads of A buffer done

        // ---- epilogue 1: y = relu(acc + aself) -> Y (bf16 hi/lo, blocked) ----
#pragma unroll
        for (int nt = 0; nt < 8; nt++) {
            int c0 = 64 * wn + 8 * nt + 2 * tig;
            float as0 = aself_s[wm * 128 + c0];
            float as1 = aself_s[wm * 128 + c0 + 1];
            int cblk = c0 >> 6, ckk = c0 & 63;
#pragma unroll
            for (int m = 0; m < 2; m++) {
                int r = 32 * wm + 16 * m + gid;
                float y00 = fmaxf(acc[m][nt][0] + as0, 0.f);
                float y01 = fmaxf(acc[m][nt][1] + as1, 0.f);
                float y10 = fmaxf(acc[m][nt][2] + as0, 0.f);
                float y11 = fmaxf(acc[m][nt][3] + as1, 0.f);
                uint32_t off0 = cblk * 16384 + swz((uint32_t)(r * 128 + ckk * 2));
                uint32_t off1 = cblk * 16384 + swz((uint32_t)((r + 8) * 128 + ckk * 2));
                uint32_t h0 = pack2(y00, y01);
                uint32_t h1 = pack2(y10, y11);
                *(uint32_t *)(sm + OAY + off0) = h0;
                *(uint32_t *)(sm + OAY + off1) = h1;
                *(uint32_t *)(sm + OAY + 32768 + off0) =
                    pack2(y00 - lo_f(h0), y01 - hi_f(h0));
                *(uint32_t *)(sm + OAY + 32768 + off1) =
                    pack2(y10 - lo_f(h1), y11 - hi_f(h1));
            }
        }
        __syncthreads();

        // ---- GEMM2: K=128, A = y (SMEM), B = eW2, pipelined ----
#pragma unroll
        for (int m = 0; m < 2; m++)
#pragma unroll
            for (int nt = 0; nt < 8; nt++)
#pragma unroll
                for (int j = 0; j < 4; j++) acc[m][nt][j] = 0.f;

        ldA(sbase + OAY, sbase + OAY + 32768, ak, AH[0], AL[0]);
        ldB(sbase + OB2H, sbase + OB2L, bk, BH[0], BL[0]);
#pragma unroll
        for (int ks = 0; ks < 8; ks++) {
            const int cur = ks & 1, nxt = cur ^ 1;
            if (ks + 1 < 8) {
                const int k2 = ks + 1, cb = k2 >> 2;
                ldA(sbase + OAY + cb * 16384, sbase + OAY + 32768 + cb * 16384,
                    (k2 & 3) * 16 + ak, AH[nxt], AL[nxt]);
                ldB(sbase + OB2H + cb * 16384, sbase + OB2L + cb * 16384,
                    (k2 & 3) * 16 + bk, BH[nxt], BL[nxt]);
            }
#pragma unroll
            for (int m = 0; m < 2; m++)
#pragma unroll
                for (int p = 0; p < 4; p++) {
                    mma16816(acc[m][2 * p], AH[cur][m], &BH[cur][p][0]);
                    mma16816(acc[m][2 * p + 1], AH[cur][m], &BH[cur][p][2]);
                }
#pragma unroll
            for (int m = 0; m < 2; m++)
#pragma unroll
                for (int p = 0; p < 4; p++) {
                    mma16816(acc[m][2 * p], AH[cur][m], &BL[cur][p][0]);
                    mma16816(acc[m][2 * p + 1], AH[cur][m], &BL[cur][p][2]);
                }
#pragma unroll
            for (int m = 0; m < 2; m++)
#pragma unroll
                for (int p = 0; p < 4; p++) {
                    mma16816(acc[m][2 * p], AL[cur][m], &BH[cur][p][0]);
                    mma16816(acc[m][2 * p + 1], AL[cur][m], &BH[cur][p][2]);
                }
        }

        // ---- epilogue 2: z = relu(acc+eb2); g_mi[node] = sum_k mask*z ----
        {
            float mk[2][2];
#pragma unroll
            for (int m = 0; m < 2; m++) {
                mk[m][0] = mask_s[32 * wm + 16 * m + gid];
                mk[m][1] = mask_s[32 * wm + 16 * m + gid + 8];
            }
#pragma unroll
            for (int nt = 0; nt < 8; nt++) {
                int c0 = 64 * wn + 8 * nt + 2 * tig;
                float eb0 = eb2[c0], eb1v = eb2[c0 + 1];
                float s0 = 0.f, s1 = 0.f;
#pragma unroll
                for (int m = 0; m < 2; m++) {
                    s0 += mk[m][0] * fmaxf(acc[m][nt][0] + eb0, 0.f) +
                          mk[m][1] * fmaxf(acc[m][nt][2] + eb0, 0.f);
                    s1 += mk[m][0] * fmaxf(acc[m][nt][1] + eb1v, 0.f) +
                          mk[m][1] * fmaxf(acc[m][nt][3] + eb1v, 0.f);
                }
#pragma unroll
                for (int o = 4; o <= 16; o <<= 1) {
                    s0 += __shfl_xor_sync(0xffffffffu, s0, o);
                    s1 += __shfl_xor_sync(0xffffffffu, s1, o);
                }
                if (lane < 4) {
                    g_mi[(size_t)(nb0 + wm) * 128 + c0] = s0;
                    g_mi[(size_t)(nb0 + wm) * 128 + c0 + 1] = s1;
                }
            }
        }
    }
}

// ---------------------------------------------------------------------------
// Kernel 3: node MLP (FFMA2)
// ---------------------------------------------------------------------------
__global__ __launch_bounds__(256, 1) void node_kernel(
    const float *__restrict__ h_self, const float *__restrict__ nW1,
    const float *__restrict__ nb1, const float *__restrict__ nW2,
    const float *__restrict__ nb2, float *__restrict__ out) {
    float *sW2 = smem;
    float *sWc = sW2 + 16384;
    float *sU = sWc + 4096;
    float *b1s = sU + 16896;
    float *b2s = b1s + 128;
    const int tid = threadIdx.x;

    for (int i = tid; i < 16384 / 4; i += 256)
        ((float4 *)sW2)[i] = ((const float4 *)nW2)[i];
    if (tid < 128) {
        b1s[tid] = nb1[tid];
        b2s[tid] = nb2[tid];
    }

    const int m0 = (tid & 15) * 8;
    const int n0 = (tid >> 4) * 8;
    const int row0 = blockIdx.x * 128;
    const int lg = tid & 7, lr0 = tid >> 3;

    auto ldA = [&](int c, float4 *pf) {
#pragma unroll
        for (int p = 0; p < 4; p++) {
            int row = row0 + lr0 + 32 * p;
            if (row > B_ - 1) row = B_ - 1;
            const float *src = (c < 4) ? (h_self + (size_t)row * 128 + c * 32)
                                       : (g_mi + (size_t)row * 128 + (c - 4) * 32);
            pf[p] = *(const float4 *)(src + lg * 4);
        }
    };
    auto stA = [&](float4 *pf) {
#pragma unroll
        for (int p = 0; p < 4; p++) {
            int row = lr0 + 32 * p;
            float *d = sU + (lg * 4) * 132 + row;
            d[0 * 132] = pf[p].x;
            d[1 * 132] = pf[p].y;
            d[2 * 132] = pf[p].z;
            d[3 * 132] = pf[p].w;
        }
    };
    auto ldW = [&](int c, float4 *wf) {
#pragma unroll
        for (int p = 0; p < 4; p++)
            wf[p] = ((const float4 *)(nW1 + (size_t)c * 32 * 128))[tid + 256 * p];
    };
    auto stW = [&](float4 *wf) {
#pragma unroll
        for (int p = 0; p < 4; p++) ((float4 *)sWc)[tid + 256 * p] = wf[p];
    };

    float4 pa[4], pw[4];
    ldA(0, pa);
    ldW(0, pw);
    __syncthreads();
    stA(pa);
    stW(pw);
    __syncthreads();

    unsigned long long acc[32];
#pragma unroll
    for (int i = 0; i < 32; i++) acc[i] = 0ull;

    for (int c = 0; c < 8; c++) {
        float4 pa2[4], pw2[4];
        if (c < 7) {
            ldA(c + 1, pa2);
            ldW(c + 1, pw2);
        }
        const float *xb = sU + m0;
        const float *wb = sWc + n0;
#pragma unroll 8
        for (int kk = 0; kk < 32; kk++)
            mm_step(xb + kk * 132, wb + kk * 128, acc);
        __syncthreads();
        if (c < 7) {
            stA(pa2);
            stW(pw2);
            __syncthreads();
        }
    }
#pragma unroll
    for (int j = 0; j < 8; j++) {
        float bv = b1s[n0 + j];
#pragma unroll
        for (int i2 = 0; i2 < 4; i2++) {
            float2 v = unpk(acc[i2 * 8 + j]);
            sU[(n0 + j) * 132 + m0 + 2 * i2] = fmaxf(v.x + bv, 0.f);
            sU[(n0 + j) * 132 + m0 + 2 * i2 + 1] = fmaxf(v.y + bv, 0.f);
        }
    }
    __syncthreads();
#pragma unroll
    for (int i = 0; i < 32; i++) acc[i] = 0ull;
    {
        const float *xb = sU + m0;
        const float *wb = sW2 + n0;
#pragma unroll 8
        for (int k = 0; k < 128; k++)
            mm_step(xb + k * 132, wb + k * 128, acc);
    }
    __syncthreads();
#pragma unroll
    for (int j = 0; j < 8; j++) {
        float bv = b2s[n0 + j];
#pragma unroll
        for (int i2 = 0; i2 < 4; i2++) {
            float2 v = unpk(acc[i2 * 8 + j]);
            sU[(m0 + 2 * i2) * 132 + n0 + j] = fmaxf(v.x + bv, 0.f);
            sU[(m0 + 2 * i2 + 1) * 132 + n0 + j] = fmaxf(v.y + bv, 0.f);
        }
    }
    __syncthreads();
#pragma unroll
    for (int p = 0; p < 16; p++) {
        int q = tid + 256 * p;
        int row = q >> 5;
        int c4 = (q & 31) * 4;
        int grow = row0 + row;
        if (grow < B_)
            *(float4 *)(out + (size_t)grow * 128 + c4) =
                *(const float4 *)(sU + row * 132 + c4);
    }
}

// ---------------------------------------------------------------------------
extern "C" void kernel_launch(void *const *d_in, const int *in_sizes, int n_in,
                              void *d_out, int out_size) {
    const float *h_self = (const float *)d_in[0];
    const float *h_nei = (const float *)d_in[1];
    const float *e_ij = (const float *)d_in[2];
    const float *mask = (const float *)d_in[3];
    const float *eW1 = (const float *)d_in[4];
    const float *eb1 = (const float *)d_in[5];
    const float *eW2 = (const float *)d_in[6];
    const float *eb2 = (const float *)d_in[7];
    const float *nW1 = (const float *)d_in[8];
    const float *nb1 = (const float *)d_in[9];
    const float *nW2 = (const float *)d_in[10];
    const float *nb2 = (const float *)d_in[11];
    float *out = (float *)d_out;

    const int SMEM_A = (16384 + 16896 + 128) * 4;
    const int SMEM_C = (16384 + 4096 + 16896 + 256) * 4;

    cudaFuncSetAttribute(self_kernel, cudaFuncAttributeMaxDynamicSharedMemorySize,
                         SMEM_A);
    cudaFuncSetAttribute(edge_mma_kernel,
                         cudaFuncAttributeMaxDynamicSharedMemorySize, EDGE_SMEM);
    cudaFuncSetAttribute(node_kernel, cudaFuncAttributeMaxDynamicSharedMemorySize,
                         SMEM_C);

    int dev = 0, nsm = 148;
    cudaGetDevice(&dev);
    cudaDeviceGetAttribute(&nsm, cudaDevAttrMultiProcessorCount, dev);

    const int tilesAC = (B_ + 127) / 128;  // 391
    const int ntilesB = B_ / 4;            // 12500

    self_kernel<<<tilesAC, 256, SMEM_A>>>(h_self, eW1, eb1);
    edge_mma_kernel<<<nsm, 256, EDGE_SMEM>>>(h_nei, e_ij, mask, eW1, eW2, eb2,
                                             ntilesB);
    node_kernel<<<tilesAC, 256, SMEM_C>>>(h_self, nW1, nb1, nW2, nb2, out);
}

// round 9
// speedup vs baseline: 3.9846x; 1.6416x over previous
#include <cuda_runtime.h>
#include <cuda_fp16.h>
#include <cstdint>
#include <cstddef>

// ---------------------------------------------------------------------------
// MPNN layer, fp32.  B=50000, K=32, D=128, E=32.
//  self_kernel : g_aself = h_self @ eW1[0:128] + eb1              (FFMA2)
//  edge_mma    : per 128-row tile (4 nodes x 32 neighbors), HMMA mma.sync
//                SINGLE-PASS fp16 GEMMs (fp32 accumulate):
//                  y = relu(aself + [h_nei|e_ij] @ eW1[128:288])     K=160
//                  z = relu(y @ eW2 + eb2)                           K=128
//                  g_mi[node] = sum_k mask * z   (warp shuffle)
//  node_kernel : out = relu(relu([h_self|g_mi]@nW1+nb1)@nW2+nb2)  (FFMA2)
// ---------------------------------------------------------------------------

#define B_  50000
#define K_  32
#define D_  128
#define E_  32

__device__ float g_aself[(size_t)B_ * D_];
__device__ float g_mi[(size_t)B_ * D_];

// ======================= helpers ===========================================
__device__ __forceinline__ uint32_t smem_u32(const void* p) {
    uint32_t a;
    asm("{ .reg .u64 t; cvta.to.shared.u64 t, %1; cvt.u32.u64 %0, t; }"
        : "=r"(a) : "l"(p));
    return a;
}
// SW128-style swizzle: XOR bits[6:4] with bits[9:7]
__device__ __forceinline__ uint32_t swz(uint32_t b) { return b ^ ((b >> 3) & 0x70); }
// pack two fp32 -> f16x2 (a in lower half)
__device__ __forceinline__ uint32_t packh2(float a, float b) {
    uint32_t r;
    asm("cvt.rn.f16x2.f32 %0, %1, %2;" : "=r"(r) : "f"(b), "f"(a));
    return r;
}
__device__ __forceinline__ uint16_t packh1(float a) {
    uint16_t r;
    asm("cvt.rn.f16.f32 %0, %1;" : "=h"(r) : "f"(a));
    return r;
}

__device__ __forceinline__ void ldsm4(uint32_t* r, uint32_t addr) {
    asm volatile("ldmatrix.sync.aligned.m8n8.x4.shared.b16 {%0,%1,%2,%3}, [%4];"
                 : "=r"(r[0]), "=r"(r[1]), "=r"(r[2]), "=r"(r[3]) : "r"(addr));
}
// fp16 inputs, fp32 accumulator
__device__ __forceinline__ void mma16816(float* d, const uint32_t* a, const uint32_t* b) {
    asm("mma.sync.aligned.m16n8k16.row.col.f32.f16.f16.f32 "
        "{%0,%1,%2,%3}, {%4,%5,%6,%7}, {%8,%9}, {%0,%1,%2,%3};"
        : "+f"(d[0]), "+f"(d[1]), "+f"(d[2]), "+f"(d[3])
        : "r"(a[0]), "r"(a[1]), "r"(a[2]), "r"(a[3]), "r"(b[0]), "r"(b[1]));
}

// ---- packed f32x2 helpers (FFMA2 kernels) ---------------------------------
__device__ __forceinline__ unsigned long long dup2(float b) {
    unsigned long long r;
    asm("mov.b64 %0, {%1, %1};" : "=l"(r) : "f"(b));
    return r;
}
__device__ __forceinline__ void fma2(unsigned long long &d, unsigned long long a,
                                     unsigned long long b) {
    asm("fma.rn.f32x2 %0, %1, %2, %0;" : "+l"(d) : "l"(a), "l"(b));
}
__device__ __forceinline__ float2 unpk(unsigned long long v) {
    float2 r;
    asm("mov.b64 {%0, %1}, %2;" : "=f"(r.x), "=f"(r.y) : "l"(v));
    return r;
}
__device__ __forceinline__ void mm_step(const float *__restrict__ xs,
                                        const float *__restrict__ ws,
                                        unsigned long long *acc) {
    ulonglong2 a01 = *reinterpret_cast<const ulonglong2 *>(xs);
    ulonglong2 a23 = *reinterpret_cast<const ulonglong2 *>(xs + 4);
    float4 b0 = *reinterpret_cast<const float4 *>(ws);
    float4 b1 = *reinterpret_cast<const float4 *>(ws + 4);
    unsigned long long A0 = a01.x, A1 = a01.y, A2 = a23.x, A3 = a23.y;
    unsigned long long Bd[8] = {dup2(b0.x), dup2(b0.y), dup2(b0.z), dup2(b0.w),
                                dup2(b1.x), dup2(b1.y), dup2(b1.z), dup2(b1.w)};
#pragma unroll
    for (int j = 0; j < 8; j++) {
        fma2(acc[0 * 8 + j], A0, Bd[j]);
        fma2(acc[1 * 8 + j], A1, Bd[j]);
        fma2(acc[2 * 8 + j], A2, Bd[j]);
        fma2(acc[3 * 8 + j], A3, Bd[j]);
    }
}

extern __shared__ float smem[];

// ---------------------------------------------------------------------------
// Kernel 1: a_self = h_self @ eW1[0:128,:] + eb1   (FFMA2)
// ---------------------------------------------------------------------------
__global__ __launch_bounds__(256, 1) void self_kernel(
    const float *__restrict__ h_self, const float *__restrict__ eW1,
    const float *__restrict__ eb1) {
    float *sW = smem;
    float *sU = sW + 16384;
    float *eb = sU + 16896;
    const int tid = threadIdx.x;

    for (int i = tid; i < 16384 / 4; i += 256)
        ((float4 *)sW)[i] = ((const float4 *)eW1)[i];
    if (tid < 128) eb[tid] = eb1[tid];

    const int m0 = (tid & 15) * 8;
    const int n0 = (tid >> 4) * 8;
    const int row0 = blockIdx.x * 128;
    const int lg = tid & 7, lr0 = tid >> 3;

    auto ldchunk = [&](int c, float4 *pf) {
#pragma unroll
        for (int p = 0; p < 4; p++) {
            int row = row0 + lr0 + 32 * p;
            if (row > B_ - 1) row = B_ - 1;
            pf[p] = *(const float4 *)(h_self + (size_t)row * 128 + c * 32 + lg * 4);
        }
    };
    auto stchunk = [&](float4 *pf) {
#pragma unroll
        for (int p = 0; p < 4; p++) {
            int row = lr0 + 32 * p;
            float *d = sU + (lg * 4) * 132 + row;
            d[0 * 132] = pf[p].x;
            d[1 * 132] = pf[p].y;
            d[2 * 132] = pf[p].z;
            d[3 * 132] = pf[p].w;
        }
    };

    float4 pf[4];
    ldchunk(0, pf);
    __syncthreads();
    stchunk(pf);
    __syncthreads();

    unsigned long long acc[32];
#pragma unroll
    for (int i = 0; i < 32; i++) acc[i] = 0ull;

    for (int c = 0; c < 4; c++) {
        float4 pf2[4];
        if (c < 3) ldchunk(c + 1, pf2);
        const float *xb = sU + m0;
        const float *wb = sW + c * 32 * 128 + n0;
#pragma unroll 8
        for (int kk = 0; kk < 32; kk++)
            mm_step(xb + kk * 132, wb + kk * 128, acc);
        __syncthreads();
        if (c < 3) {
            stchunk(pf2);
            __syncthreads();
        }
    }
#pragma unroll
    for (int j = 0; j < 8; j++) {
        float bv = eb[n0 + j];
#pragma unroll
        for (int i2 = 0; i2 < 4; i2++) {
            float2 v = unpk(acc[i2 * 8 + j]);
            sU[(m0 + 2 * i2) * 132 + n0 + j] = v.x + bv;
            sU[(m0 + 2 * i2 + 1) * 132 + n0 + j] = v.y + bv;
        }
    }
    __syncthreads();
#pragma unroll
    for (int p = 0; p < 16; p++) {
        int q = tid + 256 * p;
        int row = q >> 5;
        int c4 = (q & 31) * 4;
        int grow = row0 + row;
        if (grow < B_)
            *(float4 *)(g_aself + (size_t)grow * 128 + c4) =
                *(const float4 *)(sU + row * 132 + c4);
    }
}

// ---------------------------------------------------------------------------
// Kernel 2: edge MLP via single-pass fp16 mma.sync. Persistent, 1 CTA/SM.
// SMEM layout (bytes): blocked [n/m 128][k 64] fp16, 128B rows, swizzled.
// ---------------------------------------------------------------------------
#define OB1 0         // eW1[128:288]^T : 3 blocks x 16384 = 49152
#define OB2 49152     // eW2^T : 2 blocks x 16384 = 32768
#define OAY 81920     // union: A chunk (16384) / Y (2 blocks = 32768)
#define OASELF 114688 // 512 floats (2048 B)
#define OMASK  116736 // 128 floats (512 B)
#define EDGE_SMEM 117248

__global__ __launch_bounds__(256, 1) void edge_mma_kernel(
    const float *__restrict__ h_nei, const float *__restrict__ e_ij,
    const float *__restrict__ mask, const float *__restrict__ eW1,
    const float *__restrict__ eW2, const float *__restrict__ eb2, int ntiles) {
    char *sm = (char *)smem;
    float *aself_s = (float *)(sm + OASELF);
    float *mask_s = (float *)(sm + OMASK);
    const int tid = threadIdx.x;
    const int wid = tid >> 5, lane = tid & 31;
    const int wm = wid & 3, wn = wid >> 2;     // 4 M-groups x 2 N-groups
    const int gid = lane >> 2, tig = lane & 3;
    const uint32_t sbase = smem_u32(sm);

    // ---- one-time: weights -> fp16, transposed [n][k] blocked ----
    for (int idx = tid; idx < 160 * 128; idx += 256) {
        int n = idx & 127, k = idx >> 7;
        int c = k >> 6, kk = k & 63;
        float w = eW1[(size_t)(128 + k) * 128 + n];
        uint32_t off = c * 16384 + swz(n * 128 + kk * 2);
        *(uint16_t *)(sm + OB1 + off) = packh1(w);
    }
    for (int idx = tid; idx < 128 * 128; idx += 256) {
        int n = idx & 127, k = idx >> 7;
        int c = k >> 6, kk = k & 63;
        float w = eW2[(size_t)k * 128 + n];
        uint32_t off = c * 16384 + swz(n * 128 + kk * 2);
        *(uint16_t *)(sm + OB2 + off) = packh1(w);
    }

    // per-thread ldmatrix lane-address components
    const int arow = lane & 15;                 // A: rows m0..m0+15
    const int ak = (lane >> 4) * 8;             // A: k-half
    const int brow = (lane & 7) + 8 * (lane >> 4);  // B: n rows
    const int bk = 8 * ((lane >> 3) & 1);       // B: k-half

    // fragment double buffers
    uint32_t AH[2][2][4], BH[2][4][4];

    auto ldA = [&](uint32_t baseA, int koff, uint32_t (&AHb)[2][4]) {
#pragma unroll
        for (int m = 0; m < 2; m++) {
            uint32_t off = swz((uint32_t)((32 * wm + 16 * m + arow) * 128 + koff * 2));
            ldsm4(AHb[m], baseA + off);
        }
    };
    auto ldB = [&](uint32_t baseB, int koff, uint32_t (&BHb)[4][4]) {
#pragma unroll
        for (int p = 0; p < 4; p++) {
            uint32_t off = swz((uint32_t)((64 * wn + 16 * p + brow) * 128 + koff * 2));
            ldsm4(BHb[p], baseB + off);
        }
    };

    __syncthreads();

    for (int tile = blockIdx.x; tile < ntiles; tile += gridDim.x) {
        const size_t rowbase = (size_t)tile * 128;
        const int nb0 = tile * 4;

        __syncthreads();  // prev tile fully done with mask_s/aself_s/OAY
        if (tid < 128) mask_s[tid] = mask[rowbase + tid];
        aself_s[tid] = g_aself[(size_t)nb0 * 128 + tid];
        aself_s[tid + 256] = g_aself[(size_t)nb0 * 128 + tid + 256];

        float acc[2][8][4];
#pragma unroll
        for (int m = 0; m < 2; m++)
#pragma unroll
            for (int nt = 0; nt < 8; nt++)
#pragma unroll
                for (int j = 0; j < 4; j++) acc[m][nt][j] = 0.f;

        // prefetch chunk 0 (h_nei k0-63)
        float4 pf[8];
#pragma unroll
        for (int i = 0; i < 8; i++) {
            int q = tid + 256 * i;
            pf[i] = *(const float4 *)(h_nei + (rowbase + (q >> 4)) * 128 + (q & 15) * 4);
        }

        // ---- GEMM1: K=160 in chunks {64,64,32}, pipelined fragments ----
#pragma unroll
        for (int c = 0; c < 3; c++) {
            __syncthreads();  // A buffer free
            if (c < 2) {
#pragma unroll
                for (int i = 0; i < 8; i++) {
                    int q = tid + 256 * i;
                    int r = q >> 4, kc = (q & 15) * 4;
                    uint32_t off = swz((uint32_t)(r * 128 + kc * 2));
                    *(uint2 *)(sm + OAY + off) =
                        make_uint2(packh2(pf[i].x, pf[i].y), packh2(pf[i].z, pf[i].w));
                }
            } else {
#pragma unroll
                for (int i = 0; i < 4; i++) {
                    int q = tid + 256 * i;
                    int r = q >> 3, kc = (q & 7) * 4;
                    uint32_t off = swz((uint32_t)(r * 128 + kc * 2));
                    *(uint2 *)(sm + OAY + off) =
                        make_uint2(packh2(pf[i].x, pf[i].y), packh2(pf[i].z, pf[i].w));
                }
            }
            __syncthreads();  // A ready
            // prefetch next chunk's global data (overlaps MMA)
            if (c == 0) {
#pragma unroll
                for (int i = 0; i < 8; i++) {
                    int q = tid + 256 * i;
                    pf[i] = *(const float4 *)(h_nei + (rowbase + (q >> 4)) * 128 + 64 +
                                              (q & 15) * 4);
                }
            } else if (c == 1) {
#pragma unroll
                for (int i = 0; i < 4; i++) {
                    int q = tid + 256 * i;
                    pf[i] = *(const float4 *)(e_ij + (rowbase + (q >> 3)) * 32 + (q & 7) * 4);
                }
            }
            const int nk = (c == 2) ? 2 : 4;
            const uint32_t aB = sbase + OAY;
            const uint32_t bB = sbase + OB1 + c * 16384;
            ldA(aB, ak, AH[0]);
            ldB(bB, bk, BH[0]);
#pragma unroll
            for (int ks = 0; ks < 4; ks++) {
                if (ks < nk) {
                    const int cur = ks & 1, nxt = cur ^ 1;
                    if (ks + 1 < nk) {
                        ldA(aB, (ks + 1) * 16 + ak, AH[nxt]);
                        ldB(bB, (ks + 1) * 16 + bk, BH[nxt]);
                    }
#pragma unroll
                    for (int m = 0; m < 2; m++)
#pragma unroll
                        for (int p = 0; p < 4; p++) {
                            mma16816(acc[m][2 * p], AH[cur][m], &BH[cur][p][0]);
                            mma16816(acc[m][2 * p + 1], AH[cur][m], &BH[cur][p][2]);
                        }
                }
            }
        }
        __syncthreads();  // all GEMM1 reads of A buffer done

        // ---- epilogue 1: y = relu(acc + aself) -> Y (fp16, blocked) ----
#pragma unroll
        for (int nt = 0; nt < 8; nt++) {
            int c0 = 64 * wn + 8 * nt + 2 * tig;
            float as0 = aself_s[wm * 128 + c0];
            float as1 = aself_s[wm * 128 + c0 + 1];
            int cblk = c0 >> 6, ckk = c0 & 63;
#pragma unroll
            for (int m = 0; m < 2; m++) {
                int r = 32 * wm + 16 * m + gid;
                float y00 = fmaxf(acc[m][nt][0] + as0, 0.f);
                float y01 = fmaxf(acc[m][nt][1] + as1, 0.f);
                float y10 = fmaxf(acc[m][nt][2] + as0, 0.f);
                float y11 = fmaxf(acc[m][nt][3] + as1, 0.f);
                uint32_t off0 = cblk * 16384 + swz((uint32_t)(r * 128 + ckk * 2));
                uint32_t off1 = cblk * 16384 + swz((uint32_t)((r + 8) * 128 + ckk * 2));
                *(uint32_t *)(sm + OAY + off0) = packh2(y00, y01);
                *(uint32_t *)(sm + OAY + off1) = packh2(y10, y11);
            }
        }
        __syncthreads();

        // ---- GEMM2: K=128, A = y (SMEM), B = eW2, pipelined ----
#pragma unroll
        for (int m = 0; m < 2; m++)
#pragma unroll
            for (int nt = 0; nt < 8; nt++)
#pragma unroll
                for (int j = 0; j < 4; j++) acc[m][nt][j] = 0.f;

        ldA(sbase + OAY, ak, AH[0]);
        ldB(sbase + OB2, bk, BH[0]);
#pragma unroll
        for (int ks = 0; ks < 8; ks++) {
            const int cur = ks & 1, nxt = cur ^ 1;
            if (ks + 1 < 8) {
                const int k2 = ks + 1, cb = k2 >> 2;
                ldA(sbase + OAY + cb * 16384, (k2 & 3) * 16 + ak, AH[nxt]);
                ldB(sbase + OB2 + cb * 16384, (k2 & 3) * 16 + bk, BH[nxt]);
            }
#pragma unroll
            for (int m = 0; m < 2; m++)
#pragma unroll
                for (int p = 0; p < 4; p++) {
                    mma16816(acc[m][2 * p], AH[cur][m], &BH[cur][p][0]);
                    mma16816(acc[m][2 * p + 1], AH[cur][m], &BH[cur][p][2]);
                }
        }

        // ---- epilogue 2: z = relu(acc+eb2); g_mi[node] = sum_k mask*z ----
        {
            float mk[2][2];
#pragma unroll
            for (int m = 0; m < 2; m++) {
                mk[m][0] = mask_s[32 * wm + 16 * m + gid];
                mk[m][1] = mask_s[32 * wm + 16 * m + gid + 8];
            }
#pragma unroll
            for (int nt = 0; nt < 8; nt++) {
                int c0 = 64 * wn + 8 * nt + 2 * tig;
                float eb0 = eb2[c0], eb1v = eb2[c0 + 1];
                float s0 = 0.f, s1 = 0.f;
#pragma unroll
                for (int m = 0; m < 2; m++) {
                    s0 += mk[m][0] * fmaxf(acc[m][nt][0] + eb0, 0.f) +
                          mk[m][1] * fmaxf(acc[m][nt][2] + eb0, 0.f);
                    s1 += mk[m][0] * fmaxf(acc[m][nt][1] + eb1v, 0.f) +
                          mk[m][1] * fmaxf(acc[m][nt][3] + eb1v, 0.f);
                }
#pragma unroll
                for (int o = 4; o <= 16; o <<= 1) {
                    s0 += __shfl_xor_sync(0xffffffffu, s0, o);
                    s1 += __shfl_xor_sync(0xffffffffu, s1, o);
                }
                if (lane < 4) {
                    g_mi[(size_t)(nb0 + wm) * 128 + c0] = s0;
                    g_mi[(size_t)(nb0 + wm) * 128 + c0 + 1] = s1;
                }
            }
        }
    }
}

// ---------------------------------------------------------------------------
// Kernel 3: node MLP (FFMA2)
// ---------------------------------------------------------------------------
__global__ __launch_bounds__(256, 1) void node_kernel(
    const float *__restrict__ h_self, const float *__restrict__ nW1,
    const float *__restrict__ nb1, const float *__restrict__ nW2,
    const float *__restrict__ nb2, float *__restrict__ out) {
    float *sW2 = smem;
    float *sWc = sW2 + 16384;
    float *sU = sWc + 4096;
    float *b1s = sU + 16896;
    float *b2s = b1s + 128;
    const int tid = threadIdx.x;

    for (int i = tid; i < 16384 / 4; i += 256)
        ((float4 *)sW2)[i] = ((const float4 *)nW2)[i];
    if (tid < 128) {
        b1s[tid] = nb1[tid];
        b2s[tid] = nb2[tid];
    }

    const int m0 = (tid & 15) * 8;
    const int n0 = (tid >> 4) * 8;
    const int row0 = blockIdx.x * 128;
    const int lg = tid & 7, lr0 = tid >> 3;

    auto ldA = [&](int c, float4 *pf) {
#pragma unroll
        for (int p = 0; p < 4; p++) {
            int row = row0 + lr0 + 32 * p;
            if (row > B_ - 1) row = B_ - 1;
            const float *src = (c < 4) ? (h_self + (size_t)row * 128 + c * 32)
                                       : (g_mi + (size_t)row * 128 + (c - 4) * 32);
            pf[p] = *(const float4 *)(src + lg * 4);
        }
    };
    auto stA = [&](float4 *pf) {
#pragma unroll
        for (int p = 0; p < 4; p++) {
            int row = lr0 + 32 * p;
            float *d = sU + (lg * 4) * 132 + row;
            d[0 * 132] = pf[p].x;
            d[1 * 132] = pf[p].y;
            d[2 * 132] = pf[p].z;
            d[3 * 132] = pf[p].w;
        }
    };
    auto ldW = [&](int c, float4 *wf) {
#pragma unroll
        for (int p = 0; p < 4; p++)
            wf[p] = ((const float4 *)(nW1 + (size_t)c * 32 * 128))[tid + 256 * p];
    };
    auto stW = [&](float4 *wf) {
#pragma unroll
        for (int p = 0; p < 4; p++) ((float4 *)sWc)[tid + 256 * p] = wf[p];
    };

    float4 pa[4], pw[4];
    ldA(0, pa);
    ldW(0, pw);
    __syncthreads();
    stA(pa);
    stW(pw);
    __syncthreads();

    unsigned long long acc[32];
#pragma unroll
    for (int i = 0; i < 32; i++) acc[i] = 0ull;

    for (int c = 0; c < 8; c++) {
        float4 pa2[4], pw2[4];
        if (c < 7) {
            ldA(c + 1, pa2);
            ldW(c + 1, pw2);
        }
        const float *xb = sU + m0;
        const float *wb = sWc + n0;
#pragma unroll 8
        for (int kk = 0; kk < 32; kk++)
            mm_step(xb + kk * 132, wb + kk * 128, acc);
        __syncthreads();
        if (c < 7) {
            stA(pa2);
            stW(pw2);
            __syncthreads();
        }
    }
#pragma unroll
    for (int j = 0; j < 8; j++) {
        float bv = b1s[n0 + j];
#pragma unroll
        for (int i2 = 0; i2 < 4; i2++) {
            float2 v = unpk(acc[i2 * 8 + j]);
            sU[(n0 + j) * 132 + m0 + 2 * i2] = fmaxf(v.x + bv, 0.f);
            sU[(n0 + j) * 132 + m0 + 2 * i2 + 1] = fmaxf(v.y + bv, 0.f);
        }
    }
    __syncthreads();
#pragma unroll
    for (int i = 0; i < 32; i++) acc[i] = 0ull;
    {
        const float *xb = sU + m0;
        const float *wb = sW2 + n0;
#pragma unroll 8
        for (int k = 0; k < 128; k++)
            mm_step(xb + k * 132, wb + k * 128, acc);
    }
    __syncthreads();
#pragma unroll
    for (int j = 0; j < 8; j++) {
        float bv = b2s[n0 + j];
#pragma unroll
        for (int i2 = 0; i2 < 4; i2++) {
            float2 v = unpk(acc[i2 * 8 + j]);
            sU[(m0 + 2 * i2) * 132 + n0 + j] = fmaxf(v.x + bv, 0.f);
            sU[(m0 + 2 * i2 + 1) * 132 + n0 + j] = fmaxf(v.y + bv, 0.f);
        }
    }
    __syncthreads();
#pragma unroll
    for (int p = 0; p < 16; p++) {
        int q = tid + 256 * p;
        int row = q >> 5;
        int c4 = (q & 31) * 4;
        int grow = row0 + row;
        if (grow < B_)
            *(float4 *)(out + (size_t)grow * 128 + c4) =
                *(const float4 *)(sU + row * 132 + c4);
    }
}

// ---------------------------------------------------------------------------
extern "C" void kernel_launch(void *const *d_in, const int *in_sizes, int n_in,
                              void *d_out, int out_size) {
    const float *h_self = (const float *)d_in[0];
    const float *h_nei = (const float *)d_in[1];
    const float *e_ij = (const float *)d_in[2];
    const float *mask = (const float *)d_in[3];
    const float *eW1 = (const float *)d_in[4];
    const float *eb1 = (const float *)d_in[5];
    const float *eW2 = (const float *)d_in[6];
    const float *eb2 = (const float *)d_in[7];
    const float *nW1 = (const float *)d_in[8];
    const float *nb1 = (const float *)d_in[9];
    const float *nW2 = (const float *)d_in[10];
    const float *nb2 = (const float *)d_in[11];
    float *out = (float *)d_out;

    const int SMEM_A = (16384 + 16896 + 128) * 4;
    const int SMEM_C = (16384 + 4096 + 16896 + 256) * 4;

    cudaFuncSetAttribute(self_kernel, cudaFuncAttributeMaxDynamicSharedMemorySize,
                         SMEM_A);
    cudaFuncSetAttribute(edge_mma_kernel,
                         cudaFuncAttributeMaxDynamicSharedMemorySize, EDGE_SMEM);
    cudaFuncSetAttribute(node_kernel, cudaFuncAttributeMaxDynamicSharedMemorySize,
                         SMEM_C);

    int dev = 0, nsm = 148;
    cudaGetDevice(&dev);
    cudaDeviceGetAttribute(&nsm, cudaDevAttrMultiProcessorCount, dev);

    const int tilesAC = (B_ + 127) / 128;  // 391
    const int ntilesB = B_ / 4;            // 12500

    self_kernel<<<tilesAC, 256, SMEM_A>>>(h_self, eW1, eb1);
    edge_mma_kernel<<<nsm, 256, EDGE_SMEM>>>(h_nei, e_ij, mask, eW1, eW2, eb2,
                                             ntilesB);
    node_kernel<<<tilesAC, 256, SMEM_C>>>(h_self, nW1, nb1, nW2, nb2, out);
}

// round 11
// speedup vs baseline: 5.0736x; 1.2733x over previous
#include <cuda_runtime.h>
#include <cuda_fp16.h>
#include <cstdint>
#include <cstddef>

// ---------------------------------------------------------------------------
// MPNN layer, fp32.  B=50000, K=32, D=128, E=32.   ALL GEMMs on fp16 HMMA.
//  self_kernel : g_aself = h_self @ eW1[0:128] + eb1
//  edge_mma    : per 128-row tile (4 nodes x 32 neighbors):
//                  y = relu(aself + [h_nei|e_ij] @ eW1[128:288])     K=160
//                  z = relu(y @ eW2 + eb2)                           K=128
//                  g_mi[node] = sum_k mask * z   (warp shuffle)
//  node_kernel : out = relu(relu([h_self|g_mi]@nW1+nb1)@nW2+nb2)    K=256,128
// ---------------------------------------------------------------------------

#define B_  50000
#define K_  32
#define D_  128
#define E_  32

__device__ float g_aself[(size_t)B_ * D_];
__device__ float g_mi[(size_t)B_ * D_];

// ======================= helpers ===========================================
__device__ __forceinline__ uint32_t smem_u32(const void* p) {
    uint32_t a;
    asm("{ .reg .u64 t; cvta.to.shared.u64 t, %1; cvt.u32.u64 %0, t; }"
        : "=r"(a) : "l"(p));
    return a;
}
__device__ __forceinline__ uint32_t swz(uint32_t b) { return b ^ ((b >> 3) & 0x70); }
__device__ __forceinline__ uint32_t packh2(float a, float b) {
    uint32_t r;
    asm("cvt.rn.f16x2.f32 %0, %1, %2;" : "=r"(r) : "f"(b), "f"(a));
    return r;
}
__device__ __forceinline__ uint16_t packh1(float a) {
    uint16_t r;
    asm("cvt.rn.f16.f32 %0, %1;" : "=h"(r) : "f"(a));
    return r;
}
__device__ __forceinline__ void ldsm4(uint32_t* r, uint32_t addr) {
    asm volatile("ldmatrix.sync.aligned.m8n8.x4.shared.b16 {%0,%1,%2,%3}, [%4];"
                 : "=r"(r[0]), "=r"(r[1]), "=r"(r[2]), "=r"(r[3]) : "r"(addr));
}
__device__ __forceinline__ void mma16816(float* d, const uint32_t* a, const uint32_t* b) {
    asm("mma.sync.aligned.m16n8k16.row.col.f32.f16.f16.f32 "
        "{%0,%1,%2,%3}, {%4,%5,%6,%7}, {%8,%9}, {%0,%1,%2,%3};"
        : "+f"(d[0]), "+f"(d[1]), "+f"(d[2]), "+f"(d[3])
        : "r"(a[0]), "r"(a[1]), "r"(a[2]), "r"(a[3]), "r"(b[0]), "r"(b[1]));
}

extern __shared__ float smem[];

// ---------------------------------------------------------------------------
// Kernel 1: a_self = h_self @ eW1[0:128,:] + eb1   (fp16 HMMA, persistent)
// ---------------------------------------------------------------------------
#define SW_OW 0       // eW1[0:128]^T fp16, 2 blocks x 16384 = 32768
#define SW_OA 32768   // A tile fp16, 2 blocks = 32768
#define SW_OEB 65536  // 128 floats
#define SELF_SMEM 66048

__global__ __launch_bounds__(256, 1) void self_kernel(
    const float *__restrict__ h_self, const float *__restrict__ eW1,
    const float *__restrict__ eb1, int ntiles) {
    char *sm = (char *)smem;
    float *ebs = (float *)(sm + SW_OEB);
    const int tid = threadIdx.x;
    const int wid = tid >> 5, lane = tid & 31;
    const int wm = wid & 3, wn = wid >> 2;
    const int gid = lane >> 2, tig = lane & 3;
    const uint32_t sbase = smem_u32(sm);

    // one-time: weights -> fp16 [n][k] blocked
    for (int idx = tid; idx < 128 * 128; idx += 256) {
        int n = idx & 127, k = idx >> 7;
        int c = k >> 6, kk = k & 63;
        uint32_t off = c * 16384 + swz(n * 128 + kk * 2);
        *(uint16_t *)(sm + SW_OW + off) = packh1(eW1[(size_t)k * 128 + n]);
    }
    if (tid < 128) ebs[tid] = eb1[tid];

    const int arow = lane & 15;
    const int ak = (lane >> 4) * 8;
    const int brow = (lane & 7) + 8 * (lane >> 4);
    const int bk = 8 * ((lane >> 3) & 1);

    uint32_t AH[2][2][4], BH[2][4][4];
    auto ldA = [&](uint32_t baseA, int koff, uint32_t (&AHb)[2][4]) {
#pragma unroll
        for (int m = 0; m < 2; m++) {
            uint32_t off = swz((uint32_t)((32 * wm + 16 * m + arow) * 128 + koff * 2));
            ldsm4(AHb[m], baseA + off);
        }
    };
    auto ldB = [&](uint32_t baseB, int koff, uint32_t (&BHb)[4][4]) {
#pragma unroll
        for (int p = 0; p < 4; p++) {
            uint32_t off = swz((uint32_t)((64 * wn + 16 * p + brow) * 128 + koff * 2));
            ldsm4(BHb[p], baseB + off);
        }
    };

    for (int tile = blockIdx.x; tile < ntiles; tile += gridDim.x) {
        const int row0 = tile * 128;
        __syncthreads();  // prev tile GEMM done reading SW_OA
#pragma unroll
        for (int i = 0; i < 16; i++) {
            int q = tid + 256 * i;
            int r = q >> 5, kc = (q & 31) * 4;
            int grow = row0 + r;
            if (grow > B_ - 1) grow = B_ - 1;
            float4 v = *(const float4 *)(h_self + (size_t)grow * 128 + kc);
            uint32_t off = (kc >> 6) * 16384 + swz((uint32_t)(r * 128 + (kc & 63) * 2));
            *(uint2 *)(sm + SW_OA + off) =
                make_uint2(packh2(v.x, v.y), packh2(v.z, v.w));
        }
        __syncthreads();

        float acc[2][8][4];
#pragma unroll
        for (int m = 0; m < 2; m++)
#pragma unroll
            for (int nt = 0; nt < 8; nt++)
#pragma unroll
                for (int j = 0; j < 4; j++) acc[m][nt][j] = 0.f;

        ldA(sbase + SW_OA, ak, AH[0]);
        ldB(sbase + SW_OW, bk, BH[0]);
#pragma unroll
        for (int ks = 0; ks < 8; ks++) {
            const int cur = ks & 1, nxt = cur ^ 1;
            if (ks + 1 < 8) {
                const int k2 = ks + 1, cb = k2 >> 2;
                ldA(sbase + SW_OA + cb * 16384, (k2 & 3) * 16 + ak, AH[nxt]);
                ldB(sbase + SW_OW + cb * 16384, (k2 & 3) * 16 + bk, BH[nxt]);
            }
#pragma unroll
            for (int m = 0; m < 2; m++)
#pragma unroll
                for (int p = 0; p < 4; p++) {
                    mma16816(acc[m][2 * p], AH[cur][m], &BH[cur][p][0]);
                    mma16816(acc[m][2 * p + 1], AH[cur][m], &BH[cur][p][2]);
                }
        }

#pragma unroll
        for (int nt = 0; nt < 8; nt++) {
            int c0 = 64 * wn + 8 * nt + 2 * tig;
            float bv0 = ebs[c0], bv1 = ebs[c0 + 1];
#pragma unroll
            for (int m = 0; m < 2; m++) {
                int r = 32 * wm + 16 * m + gid;
                int grow = row0 + r;
                if (grow < B_) {
                    float2 v = make_float2(acc[m][nt][0] + bv0, acc[m][nt][1] + bv1);
                    *(float2 *)(g_aself + (size_t)grow * 128 + c0) = v;
                }
                if (grow + 8 < B_) {
                    float2 v = make_float2(acc[m][nt][2] + bv0, acc[m][nt][3] + bv1);
                    *(float2 *)(g_aself + (size_t)(grow + 8) * 128 + c0) = v;
                }
            }
        }
    }
}

// ---------------------------------------------------------------------------
// Kernel 2: edge MLP via single-pass fp16 mma.sync. Persistent, 1 CTA/SM.
// (unchanged from R9)
// ---------------------------------------------------------------------------
#define OB1 0         // eW1[128:288]^T : 3 blocks x 16384 = 49152
#define OB2 49152     // eW2^T : 2 blocks x 16384 = 32768
#define OAY 81920     // union: A chunk (16384) / Y (2 blocks = 32768)
#define OASELF 114688 // 512 floats
#define OMASK  116736 // 128 floats
#define EDGE_SMEM 117248

__global__ __launch_bounds__(256, 1) void edge_mma_kernel(
    const float *__restrict__ h_nei, const float *__restrict__ e_ij,
    const float *__restrict__ mask, const float *__restrict__ eW1,
    const float *__restrict__ eW2, const float *__restrict__ eb2, int ntiles) {
    char *sm = (char *)smem;
    float *aself_s = (float *)(sm + OASELF);
    float *mask_s = (float *)(sm + OMASK);
    const int tid = threadIdx.x;
    const int wid = tid >> 5, lane = tid & 31;
    const int wm = wid & 3, wn = wid >> 2;
    const int gid = lane >> 2, tig = lane & 3;
    const uint32_t sbase = smem_u32(sm);

    for (int idx = tid; idx < 160 * 128; idx += 256) {
        int n = idx & 127, k = idx >> 7;
        int c = k >> 6, kk = k & 63;
        uint32_t off = c * 16384 + swz(n * 128 + kk * 2);
        *(uint16_t *)(sm + OB1 + off) = packh1(eW1[(size_t)(128 + k) * 128 + n]);
    }
    for (int idx = tid; idx < 128 * 128; idx += 256) {
        int n = idx & 127, k = idx >> 7;
        int c = k >> 6, kk = k & 63;
        uint32_t off = c * 16384 + swz(n * 128 + kk * 2);
        *(uint16_t *)(sm + OB2 + off) = packh1(eW2[(size_t)k * 128 + n]);
    }

    const int arow = lane & 15;
    const int ak = (lane >> 4) * 8;
    const int brow = (lane & 7) + 8 * (lane >> 4);
    const int bk = 8 * ((lane >> 3) & 1);

    uint32_t AH[2][2][4], BH[2][4][4];
    auto ldA = [&](uint32_t baseA, int koff, uint32_t (&AHb)[2][4]) {
#pragma unroll
        for (int m = 0; m < 2; m++) {
            uint32_t off = swz((uint32_t)((32 * wm + 16 * m + arow) * 128 + koff * 2));
            ldsm4(AHb[m], baseA + off);
        }
    };
    auto ldB = [&](uint32_t baseB, int koff, uint32_t (&BHb)[4][4]) {
#pragma unroll
        for (int p = 0; p < 4; p++) {
            uint32_t off = swz((uint32_t)((64 * wn + 16 * p + brow) * 128 + koff * 2));
            ldsm4(BHb[p], baseB + off);
        }
    };

    __syncthreads();

    for (int tile = blockIdx.x; tile < ntiles; tile += gridDim.x) {
        const size_t rowbase = (size_t)tile * 128;
        const int nb0 = tile * 4;

        __syncthreads();
        if (tid < 128) mask_s[tid] = mask[rowbase + tid];
        aself_s[tid] = g_aself[(size_t)nb0 * 128 + tid];
        aself_s[tid + 256] = g_aself[(size_t)nb0 * 128 + tid + 256];

        float acc[2][8][4];
#pragma unroll
        for (int m = 0; m < 2; m++)
#pragma unroll
            for (int nt = 0; nt < 8; nt++)
#pragma unroll
                for (int j = 0; j < 4; j++) acc[m][nt][j] = 0.f;

        float4 pf[8];
#pragma unroll
        for (int i = 0; i < 8; i++) {
            int q = tid + 256 * i;
            pf[i] = *(const float4 *)(h_nei + (rowbase + (q >> 4)) * 128 + (q & 15) * 4);
        }

#pragma unroll
        for (int c = 0; c < 3; c++) {
            __syncthreads();
            if (c < 2) {
#pragma unroll
                for (int i = 0; i < 8; i++) {
                    int q = tid + 256 * i;
                    int r = q >> 4, kc = (q & 15) * 4;
                    uint32_t off = swz((uint32_t)(r * 128 + kc * 2));
                    *(uint2 *)(sm + OAY + off) =
                        make_uint2(packh2(pf[i].x, pf[i].y), packh2(pf[i].z, pf[i].w));
                }
            } else {
#pragma unroll
                for (int i = 0; i < 4; i++) {
                    int q = tid + 256 * i;
                    int r = q >> 3, kc = (q & 7) * 4;
                    uint32_t off = swz((uint32_t)(r * 128 + kc * 2));
                    *(uint2 *)(sm + OAY + off) =
                        make_uint2(packh2(pf[i].x, pf[i].y), packh2(pf[i].z, pf[i].w));
                }
            }
            __syncthreads();
            if (c == 0) {
#pragma unroll
                for (int i = 0; i < 8; i++) {
                    int q = tid + 256 * i;
                    pf[i] = *(const float4 *)(h_nei + (rowbase + (q >> 4)) * 128 + 64 +
                                              (q & 15) * 4);
                }
            } else if (c == 1) {
#pragma unroll
                for (int i = 0; i < 4; i++) {
                    int q = tid + 256 * i;
                    pf[i] = *(const float4 *)(e_ij + (rowbase + (q >> 3)) * 32 + (q & 7) * 4);
                }
            }
            const int nk = (c == 2) ? 2 : 4;
            const uint32_t aB = sbase + OAY;
            const uint32_t bB = sbase + OB1 + c * 16384;
            ldA(aB, ak, AH[0]);
            ldB(bB, bk, BH[0]);
#pragma unroll
            for (int ks = 0; ks < 4; ks++) {
                if (ks < nk) {
                    const int cur = ks & 1, nxt = cur ^ 1;
                    if (ks + 1 < nk) {
                        ldA(aB, (ks + 1) * 16 + ak, AH[nxt]);
                        ldB(bB, (ks + 1) * 16 + bk, BH[nxt]);
                    }
#pragma unroll
                    for (int m = 0; m < 2; m++)
#pragma unroll
                        for (int p = 0; p < 4; p++) {
                            mma16816(acc[m][2 * p], AH[cur][m], &BH[cur][p][0]);
                            mma16816(acc[m][2 * p + 1], AH[cur][m], &BH[cur][p][2]);
                        }
                }
            }
        }
        __syncthreads();

#pragma unroll
        for (int nt = 0; nt < 8; nt++) {
            int c0 = 64 * wn + 8 * nt + 2 * tig;
            float as0 = aself_s[wm * 128 + c0];
            float as1 = aself_s[wm * 128 + c0 + 1];
            int cblk = c0 >> 6, ckk = c0 & 63;
#pragma unroll
            for (int m = 0; m < 2; m++) {
                int r = 32 * wm + 16 * m + gid;
                float y00 = fmaxf(acc[m][nt][0] + as0, 0.f);
                float y01 = fmaxf(acc[m][nt][1] + as1, 0.f);
                float y10 = fmaxf(acc[m][nt][2] + as0, 0.f);
                float y11 = fmaxf(acc[m][nt][3] + as1, 0.f);
                uint32_t off0 = cblk * 16384 + swz((uint32_t)(r * 128 + ckk * 2));
                uint32_t off1 = cblk * 16384 + swz((uint32_t)((r + 8) * 128 + ckk * 2));
                *(uint32_t *)(sm + OAY + off0) = packh2(y00, y01);
                *(uint32_t *)(sm + OAY + off1) = packh2(y10, y11);
            }
        }
        __syncthreads();

#pragma unroll
        for (int m = 0; m < 2; m++)
#pragma unroll
            for (int nt = 0; nt < 8; nt++)
#pragma unroll
                for (int j = 0; j < 4; j++) acc[m][nt][j] = 0.f;

        ldA(sbase + OAY, ak, AH[0]);
        ldB(sbase + OB2, bk, BH[0]);
#pragma unroll
        for (int ks = 0; ks < 8; ks++) {
            const int cur = ks & 1, nxt = cur ^ 1;
            if (ks + 1 < 8) {
                const int k2 = ks + 1, cb = k2 >> 2;
                ldA(sbase + OAY + cb * 16384, (k2 & 3) * 16 + ak, AH[nxt]);
                ldB(sbase + OB2 + cb * 16384, (k2 & 3) * 16 + bk, BH[nxt]);
            }
#pragma unroll
            for (int m = 0; m < 2; m++)
#pragma unroll
                for (int p = 0; p < 4; p++) {
                    mma16816(acc[m][2 * p], AH[cur][m], &BH[cur][p][0]);
                    mma16816(acc[m][2 * p + 1], AH[cur][m], &BH[cur][p][2]);
                }
        }

        {
            float mk[2][2];
#pragma unroll
            for (int m = 0; m < 2; m++) {
                mk[m][0] = mask_s[32 * wm + 16 * m + gid];
                mk[m][1] = mask_s[32 * wm + 16 * m + gid + 8];
            }
#pragma unroll
            for (int nt = 0; nt < 8; nt++) {
                int c0 = 64 * wn + 8 * nt + 2 * tig;
                float eb0 = eb2[c0], eb1v = eb2[c0 + 1];
                float s0 = 0.f, s1 = 0.f;
#pragma unroll
                for (int m = 0; m < 2; m++) {
                    s0 += mk[m][0] * fmaxf(acc[m][nt][0] + eb0, 0.f) +
                          mk[m][1] * fmaxf(acc[m][nt][2] + eb0, 0.f);
                    s1 += mk[m][0] * fmaxf(acc[m][nt][1] + eb1v, 0.f) +
                          mk[m][1] * fmaxf(acc[m][nt][3] + eb1v, 0.f);
                }
#pragma unroll
                for (int o = 4; o <= 16; o <<= 1) {
                    s0 += __shfl_xor_sync(0xffffffffu, s0, o);
                    s1 += __shfl_xor_sync(0xffffffffu, s1, o);
                }
                if (lane < 4) {
                    g_mi[(size_t)(nb0 + wm) * 128 + c0] = s0;
                    g_mi[(size_t)(nb0 + wm) * 128 + c0 + 1] = s1;
                }
            }
        }
    }
}

// ---------------------------------------------------------------------------
// Kernel 3: node MLP (fp16 HMMA, persistent).
//   h1 = relu([h_self|g_mi] @ nW1 + nb1)   K=256
//   out = relu(h1 @ nW2 + nb2)             K=128
// ---------------------------------------------------------------------------
#define ND_OW1 0       // nW1^T : 4 blocks x 16384 = 65536
#define ND_OW2 65536   // nW2^T : 2 blocks = 32768
#define ND_OA  98304   // A fp16 4 blocks = 65536 (Y reuses blocks 0-1)
#define ND_OB1 163840  // 128 floats
#define ND_OB2 164352  // 128 floats
#define NODE_SMEM 164864

__global__ __launch_bounds__(256, 1) void node_kernel(
    const float *__restrict__ h_self, const float *__restrict__ nW1,
    const float *__restrict__ nb1, const float *__restrict__ nW2,
    const float *__restrict__ nb2, float *__restrict__ out, int ntiles) {
    char *sm = (char *)smem;
    float *b1s = (float *)(sm + ND_OB1);
    float *b2s = (float *)(sm + ND_OB2);
    const int tid = threadIdx.x;
    const int wid = tid >> 5, lane = tid & 31;
    const int wm = wid & 3, wn = wid >> 2;
    const int gid = lane >> 2, tig = lane & 3;
    const uint32_t sbase = smem_u32(sm);

    for (int idx = tid; idx < 256 * 128; idx += 256) {
        int n = idx & 127, k = idx >> 7;
        int c = k >> 6, kk = k & 63;
        uint32_t off = c * 16384 + swz(n * 128 + kk * 2);
        *(uint16_t *)(sm + ND_OW1 + off) = packh1(nW1[(size_t)k * 128 + n]);
    }
    for (int idx = tid; idx < 128 * 128; idx += 256) {
        int n = idx & 127, k = idx >> 7;
        int c = k >> 6, kk = k & 63;
        uint32_t off = c * 16384 + swz(n * 128 + kk * 2);
        *(uint16_t *)(sm + ND_OW2 + off) = packh1(nW2[(size_t)k * 128 + n]);
    }
    if (tid < 128) {
        b1s[tid] = nb1[tid];
        b2s[tid] = nb2[tid];
    }

    const int arow = lane & 15;
    const int ak = (lane >> 4) * 8;
    const int brow = (lane & 7) + 8 * (lane >> 4);
    const int bk = 8 * ((lane >> 3) & 1);

    uint32_t AH[2][2][4], BH[2][4][4];
    auto ldA = [&](uint32_t baseA, int koff, uint32_t (&AHb)[2][4]) {
#pragma unroll
        for (int m = 0; m < 2; m++) {
            uint32_t off = swz((uint32_t)((32 * wm + 16 * m + arow) * 128 + koff * 2));
            ldsm4(AHb[m], baseA + off);
        }
    };
    auto ldB = [&](uint32_t baseB, int koff, uint32_t (&BHb)[4][4]) {
#pragma unroll
        for (int p = 0; p < 4; p++) {
            uint32_t off = swz((uint32_t)((64 * wn + 16 * p + brow) * 128 + koff * 2));
            ldsm4(BHb[p], baseB + off);
        }
    };

    for (int tile = blockIdx.x; tile < ntiles; tile += gridDim.x) {
        const int row0 = tile * 128;
        __syncthreads();  // prev tile done with ND_OA
        // A = [h_self | g_mi] -> fp16 blocked: blocks 0-1 h_self, 2-3 g_mi
#pragma unroll
        for (int i = 0; i < 16; i++) {
            int q = tid + 256 * i;
            int r = q >> 5, kc = (q & 31) * 4;
            int grow = row0 + r;
            if (grow > B_ - 1) grow = B_ - 1;
            float4 v = *(const float4 *)(h_self + (size_t)grow * 128 + kc);
            uint32_t off = (kc >> 6) * 16384 + swz((uint32_t)(r * 128 + (kc & 63) * 2));
            *(uint2 *)(sm + ND_OA + off) =
                make_uint2(packh2(v.x, v.y), packh2(v.z, v.w));
        }
#pragma unroll
        for (int i = 0; i < 16; i++) {
            int q = tid + 256 * i;
            int r = q >> 5, kc = (q & 31) * 4;
            int grow = row0 + r;
            if (grow > B_ - 1) grow = B_ - 1;
            float4 v = *(const float4 *)(g_mi + (size_t)grow * 128 + kc);
            uint32_t off =
                (2 + (kc >> 6)) * 16384 + swz((uint32_t)(r * 128 + (kc & 63) * 2));
            *(uint2 *)(sm + ND_OA + off) =
                make_uint2(packh2(v.x, v.y), packh2(v.z, v.w));
        }
        __syncthreads();

        float acc[2][8][4];
#pragma unroll
        for (int m = 0; m < 2; m++)
#pragma unroll
            for (int nt = 0; nt < 8; nt++)
#pragma unroll
                for (int j = 0; j < 4; j++) acc[m][nt][j] = 0.f;

        // GEMM1: K=256 (16 ksteps)
        ldA(sbase + ND_OA, ak, AH[0]);
        ldB(sbase + ND_OW1, bk, BH[0]);
#pragma unroll
        for (int ks = 0; ks < 16; ks++) {
            const int cur = ks & 1, nxt = cur ^ 1;
            if (ks + 1 < 16) {
                const int k2 = ks + 1, cb = k2 >> 2;
                ldA(sbase + ND_OA + cb * 16384, (k2 & 3) * 16 + ak, AH[nxt]);
                ldB(sbase + ND_OW1 + cb * 16384, (k2 & 3) * 16 + bk, BH[nxt]);
            }
#pragma unroll
            for (int m = 0; m < 2; m++)
#pragma unroll
                for (int p = 0; p < 4; p++) {
                    mma16816(acc[m][2 * p], AH[cur][m], &BH[cur][p][0]);
                    mma16816(acc[m][2 * p + 1], AH[cur][m], &BH[cur][p][2]);
                }
        }
        __syncthreads();  // all GEMM1 reads done before Y overwrites blocks 0-1

        // epilogue 1: h1 = relu(acc + b1) -> fp16 into ND_OA blocks 0-1
#pragma unroll
        for (int nt = 0; nt < 8; nt++) {
            int c0 = 64 * wn + 8 * nt + 2 * tig;
            float bv0 = b1s[c0], bv1 = b1s[c0 + 1];
            int cblk = c0 >> 6, ckk = c0 & 63;
#pragma unroll
            for (int m = 0; m < 2; m++) {
                int r = 32 * wm + 16 * m + gid;
                float y00 = fmaxf(acc[m][nt][0] + bv0, 0.f);
                float y01 = fmaxf(acc[m][nt][1] + bv1, 0.f);
                float y10 = fmaxf(acc[m][nt][2] + bv0, 0.f);
                float y11 = fmaxf(acc[m][nt][3] + bv1, 0.f);
                uint32_t off0 = cblk * 16384 + swz((uint32_t)(r * 128 + ckk * 2));
                uint32_t off1 = cblk * 16384 + swz((uint32_t)((r + 8) * 128 + ckk * 2));
                *(uint32_t *)(sm + ND_OA + off0) = packh2(y00, y01);
                *(uint32_t *)(sm + ND_OA + off1) = packh2(y10, y11);
            }
        }
        __syncthreads();

        // GEMM2: K=128
#pragma unroll
        for (int m = 0; m < 2; m++)
#pragma unroll
            for (int nt = 0; nt < 8; nt++)
#pragma unroll
                for (int j = 0; j < 4; j++) acc[m][nt][j] = 0.f;

        ldA(sbase + ND_OA, ak, AH[0]);
        ldB(sbase + ND_OW2, bk, BH[0]);
#pragma unroll
        for (int ks = 0; ks < 8; ks++) {
            const int cur = ks & 1, nxt = cur ^ 1;
            if (ks + 1 < 8) {
                const int k2 = ks + 1, cb = k2 >> 2;
                ldA(sbase + ND_OA + cb * 16384, (k2 & 3) * 16 + ak, AH[nxt]);
                ldB(sbase + ND_OW2 + cb * 16384, (k2 & 3) * 16 + bk, BH[nxt]);
            }
#pragma unroll
            for (int m = 0; m < 2; m++)
#pragma unroll
                for (int p = 0; p < 4; p++) {
                    mma16816(acc[m][2 * p], AH[cur][m], &BH[cur][p][0]);
                    mma16816(acc[m][2 * p + 1], AH[cur][m], &BH[cur][p][2]);
                }
        }

        // epilogue 2: out = relu(acc + b2)
#pragma unroll
        for (int nt = 0; nt < 8; nt++) {
            int c0 = 64 * wn + 8 * nt + 2 * tig;
            float bv0 = b2s[c0], bv1 = b2s[c0 + 1];
#pragma unroll
            for (int m = 0; m < 2; m++) {
                int r = 32 * wm + 16 * m + gid;
                int grow = row0 + r;
                if (grow < B_) {
                    float2 v = make_float2(fmaxf(acc[m][nt][0] + bv0, 0.f),
                                           fmaxf(acc[m][nt][1] + bv1, 0.f));
                    *(float2 *)(out + (size_t)grow * 128 + c0) = v;
                }
                if (grow + 8 < B_) {
                    float2 v = make_float2(fmaxf(acc[m][nt][2] + bv0, 0.f),
                                           fmaxf(acc[m][nt][3] + bv1, 0.f));
                    *(float2 *)(out + (size_t)(grow + 8) * 128 + c0) = v;
                }
            }
        }
    }
}

// ---------------------------------------------------------------------------
extern "C" void kernel_launch(void *const *d_in, const int *in_sizes, int n_in,
                              void *d_out, int out_size) {
    const float *h_self = (const float *)d_in[0];
    const float *h_nei = (const float *)d_in[1];
    const float *e_ij = (const float *)d_in[2];
    const float *mask = (const float *)d_in[3];
    const float *eW1 = (const float *)d_in[4];
    const float *eb1 = (const float *)d_in[5];
    const float *eW2 = (const float *)d_in[6];
    const float *eb2 = (const float *)d_in[7];
    const float *nW1 = (const float *)d_in[8];
    const float *nb1 = (const float *)d_in[9];
    const float *nW2 = (const float *)d_in[10];
    const float *nb2 = (const float *)d_in[11];
    float *out = (float *)d_out;

    cudaFuncSetAttribute(self_kernel, cudaFuncAttributeMaxDynamicSharedMemorySize,
                         SELF_SMEM);
    cudaFuncSetAttribute(edge_mma_kernel,
                         cudaFuncAttributeMaxDynamicSharedMemorySize, EDGE_SMEM);
    cudaFuncSetAttribute(node_kernel, cudaFuncAttributeMaxDynamicSharedMemorySize,
                         NODE_SMEM);

    int dev = 0, nsm = 148;
    cudaGetDevice(&dev);
    cudaDeviceGetAttribute(&nsm, cudaDevAttrMultiProcessorCount, dev);

    const int tilesAC = (B_ + 127) / 128;  // 391
    const int ntilesB = B_ / 4;            // 12500

    self_kernel<<<nsm, 256, SELF_SMEM>>>(h_self, eW1, eb1, tilesAC);
    edge_mma_kernel<<<nsm, 256, EDGE_SMEM>>>(h_nei, e_ij, mask, eW1, eW2, eb2,
                                             ntilesB);
    node_kernel<<<nsm, 256, NODE_SMEM>>>(h_self, nW1, nb1, nW2, nb2, out, tilesAC);
}

// round 12
// speedup vs baseline: 5.5836x; 1.1005x over previous
#include <cuda_runtime.h>
#include <cuda_fp16.h>
#include <cstdint>
#include <cstddef>

// ---------------------------------------------------------------------------
// MPNN layer, fp32.  B=50000, K=32, D=128, E=32.   ALL GEMMs on fp16 HMMA.
//  self_kernel : g_aself = h_self @ eW1[0:128] + eb1
//  edge_mma    : per 256-row tile (8 nodes x 32 neighbors), 512 threads,
//                cp.async-staged A, fp16 HMMA:
//                  y = relu(aself + [h_nei|e_ij] @ eW1[128:288])     K=160
//                  z = relu(y @ eW2 + eb2)                           K=128
//                  g_mi[node] = sum_k mask * z   (warp shuffle)
//  node_kernel : out = relu(relu([h_self|g_mi]@nW1+nb1)@nW2+nb2)    K=256,128
// ---------------------------------------------------------------------------

#define B_  50000
#define K_  32
#define D_  128
#define E_  32

__device__ float g_aself[(size_t)B_ * D_];
__device__ float g_mi[(size_t)B_ * D_];

// ======================= helpers ===========================================
__device__ __forceinline__ uint32_t smem_u32(const void* p) {
    uint32_t a;
    asm("{ .reg .u64 t; cvta.to.shared.u64 t, %1; cvt.u32.u64 %0, t; }"
        : "=r"(a) : "l"(p));
    return a;
}
__device__ __forceinline__ uint32_t swz(uint32_t b) { return b ^ ((b >> 3) & 0x70); }
__device__ __forceinline__ uint32_t packh2(float a, float b) {
    uint32_t r;
    asm("cvt.rn.f16x2.f32 %0, %1, %2;" : "=r"(r) : "f"(b), "f"(a));
    return r;
}
__device__ __forceinline__ uint16_t packh1(float a) {
    uint16_t r;
    asm("cvt.rn.f16.f32 %0, %1;" : "=h"(r) : "f"(a));
    return r;
}
__device__ __forceinline__ void ldsm4(uint32_t* r, uint32_t addr) {
    asm volatile("ldmatrix.sync.aligned.m8n8.x4.shared.b16 {%0,%1,%2,%3}, [%4];"
                 : "=r"(r[0]), "=r"(r[1]), "=r"(r[2]), "=r"(r[3]) : "r"(addr));
}
__device__ __forceinline__ void mma16816(float* d, const uint32_t* a, const uint32_t* b) {
    asm("mma.sync.aligned.m16n8k16.row.col.f32.f16.f16.f32 "
        "{%0,%1,%2,%3}, {%4,%5,%6,%7}, {%8,%9}, {%0,%1,%2,%3};"
        : "+f"(d[0]), "+f"(d[1]), "+f"(d[2]), "+f"(d[3])
        : "r"(a[0]), "r"(a[1]), "r"(a[2]), "r"(a[3]), "r"(b[0]), "r"(b[1]));
}
#define CP_ASYNC16(dst, src) \
    asm volatile("cp.async.cg.shared.global [%0], [%1], 16;" :: "r"(dst), "l"(src))
#define CP_COMMIT() asm volatile("cp.async.commit_group;" ::: "memory")
#define CP_WAIT0()  asm volatile("cp.async.wait_group 0;" ::: "memory")

extern __shared__ float smem[];

// ---------------------------------------------------------------------------
// Kernel 1: a_self = h_self @ eW1[0:128,:] + eb1   (fp16 HMMA, persistent)
// ---------------------------------------------------------------------------
#define SW_OW 0
#define SW_OA 32768
#define SW_OEB 65536
#define SELF_SMEM 66048

__global__ __launch_bounds__(256, 1) void self_kernel(
    const float *__restrict__ h_self, const float *__restrict__ eW1,
    const float *__restrict__ eb1, int ntiles) {
    char *sm = (char *)smem;
    float *ebs = (float *)(sm + SW_OEB);
    const int tid = threadIdx.x;
    const int wid = tid >> 5, lane = tid & 31;
    const int wm = wid & 3, wn = wid >> 2;
    const int gid = lane >> 2, tig = lane & 3;
    const uint32_t sbase = smem_u32(sm);

    for (int idx = tid; idx < 128 * 128; idx += 256) {
        int n = idx & 127, k = idx >> 7;
        int c = k >> 6, kk = k & 63;
        uint32_t off = c * 16384 + swz(n * 128 + kk * 2);
        *(uint16_t *)(sm + SW_OW + off) = packh1(eW1[(size_t)k * 128 + n]);
    }
    if (tid < 128) ebs[tid] = eb1[tid];

    const int arow = lane & 15;
    const int ak = (lane >> 4) * 8;
    const int brow = (lane & 7) + 8 * (lane >> 4);
    const int bk = 8 * ((lane >> 3) & 1);

    uint32_t AH[2][2][4], BH[2][4][4];
    auto ldA = [&](uint32_t baseA, int koff, uint32_t (&AHb)[2][4]) {
#pragma unroll
        for (int m = 0; m < 2; m++) {
            uint32_t off = swz((uint32_t)((32 * wm + 16 * m + arow) * 128 + koff * 2));
            ldsm4(AHb[m], baseA + off);
        }
    };
    auto ldB = [&](uint32_t baseB, int koff, uint32_t (&BHb)[4][4]) {
#pragma unroll
        for (int p = 0; p < 4; p++) {
            uint32_t off = swz((uint32_t)((64 * wn + 16 * p + brow) * 128 + koff * 2));
            ldsm4(BHb[p], baseB + off);
        }
    };

    for (int tile = blockIdx.x; tile < ntiles; tile += gridDim.x) {
        const int row0 = tile * 128;
        __syncthreads();
#pragma unroll
        for (int i = 0; i < 16; i++) {
            int q = tid + 256 * i;
            int r = q >> 5, kc = (q & 31) * 4;
            int grow = row0 + r;
            if (grow > B_ - 1) grow = B_ - 1;
            float4 v = *(const float4 *)(h_self + (size_t)grow * 128 + kc);
            uint32_t off = (kc >> 6) * 16384 + swz((uint32_t)(r * 128 + (kc & 63) * 2));
            *(uint2 *)(sm + SW_OA + off) =
                make_uint2(packh2(v.x, v.y), packh2(v.z, v.w));
        }
        __syncthreads();

        float acc[2][8][4];
#pragma unroll
        for (int m = 0; m < 2; m++)
#pragma unroll
            for (int nt = 0; nt < 8; nt++)
#pragma unroll
                for (int j = 0; j < 4; j++) acc[m][nt][j] = 0.f;

        ldA(sbase + SW_OA, ak, AH[0]);
        ldB(sbase + SW_OW, bk, BH[0]);
#pragma unroll
        for (int ks = 0; ks < 8; ks++) {
            const int cur = ks & 1, nxt = cur ^ 1;
            if (ks + 1 < 8) {
                const int k2 = ks + 1, cb = k2 >> 2;
                ldA(sbase + SW_OA + cb * 16384, (k2 & 3) * 16 + ak, AH[nxt]);
                ldB(sbase + SW_OW + cb * 16384, (k2 & 3) * 16 + bk, BH[nxt]);
            }
#pragma unroll
            for (int m = 0; m < 2; m++)
#pragma unroll
                for (int p = 0; p < 4; p++) {
                    mma16816(acc[m][2 * p], AH[cur][m], &BH[cur][p][0]);
                    mma16816(acc[m][2 * p + 1], AH[cur][m], &BH[cur][p][2]);
                }
        }

#pragma unroll
        for (int nt = 0; nt < 8; nt++) {
            int c0 = 64 * wn + 8 * nt + 2 * tig;
            float bv0 = ebs[c0], bv1 = ebs[c0 + 1];
#pragma unroll
            for (int m = 0; m < 2; m++) {
                int r = 32 * wm + 16 * m + gid;
                int grow = row0 + r;
                if (grow < B_) {
                    float2 v = make_float2(acc[m][nt][0] + bv0, acc[m][nt][1] + bv1);
                    *(float2 *)(g_aself + (size_t)grow * 128 + c0) = v;
                }
                if (grow + 8 < B_) {
                    float2 v = make_float2(acc[m][nt][2] + bv0, acc[m][nt][3] + bv1);
                    *(float2 *)(g_aself + (size_t)(grow + 8) * 128 + c0) = v;
                }
            }
        }
    }
}

// ---------------------------------------------------------------------------
// Kernel 2: edge MLP. 512 threads, 256-row tiles (8 nodes), cp.async staging.
// SMEM blocks: weights blocked [n128][k64] fp16; A/Y blocked [r256][k64] fp16.
// ---------------------------------------------------------------------------
#define OB1 0          // eW1[128:288]^T : 3 blocks x 16384 = 49152
#define OB2 49152      // eW2^T : 2 blocks = 32768
#define OAY 81920      // union: A chunk (32768) / Y (2 blocks x 32768 = 65536)
#define OST 147456     // fp32 cp.async staging, 65536
#define OASELF 212992  // 1024 floats (4096 B)
#define OMASK  217088  // 256 floats (1024 B)
#define OEB2   218112  // 128 floats (512 B)
#define EDGE_SMEM 218624

__global__ __launch_bounds__(512, 1) void edge_mma_kernel(
    const float *__restrict__ h_nei, const float *__restrict__ e_ij,
    const float *__restrict__ mask, const float *__restrict__ eW1,
    const float *__restrict__ eW2, const float *__restrict__ eb2, int ntiles) {
    char *sm = (char *)smem;
    float *aself_s = (float *)(sm + OASELF);
    float *mask_s = (float *)(sm + OMASK);
    float *eb2_s = (float *)(sm + OEB2);
    const int tid = threadIdx.x;
    const int wid = tid >> 5, lane = tid & 31;
    const int wm = wid & 7, wn = wid >> 3;   // 8 M-groups x 2 N-groups
    const int gid = lane >> 2, tig = lane & 3;
    const uint32_t sbase = smem_u32(sm);

    auto issue_cp = [&](int t2, int c) {
        const size_t rb = (size_t)t2 * 256;
        if (c < 2) {
#pragma unroll
            for (int i = 0; i < 8; i++) {
                int q = tid + 512 * i;
                uint32_t dst = sbase + OST + q * 16;
                const float *src = h_nei + (rb + (q >> 4)) * 128 + c * 64 + (q & 15) * 4;
                CP_ASYNC16(dst, src);
            }
        } else {
#pragma unroll
            for (int i = 0; i < 4; i++) {
                int q = tid + 512 * i;
                uint32_t dst = sbase + OST + q * 16;
                const float *src = e_ij + (rb + (q >> 3)) * 32 + (q & 7) * 4;
                CP_ASYNC16(dst, src);
            }
        }
        CP_COMMIT();
    };

    // prologue DMA (overlaps weight conversion below)
    int tile = blockIdx.x;
    if (tile < ntiles) issue_cp(tile, 0);

    // one-time: weights -> fp16 [n][k] blocked
    for (int idx = tid; idx < 160 * 128; idx += 512) {
        int n = idx & 127, k = idx >> 7;
        int c = k >> 6, kk = k & 63;
        uint32_t off = c * 16384 + swz(n * 128 + kk * 2);
        *(uint16_t *)(sm + OB1 + off) = packh1(eW1[(size_t)(128 + k) * 128 + n]);
    }
    for (int idx = tid; idx < 128 * 128; idx += 512) {
        int n = idx & 127, k = idx >> 7;
        int c = k >> 6, kk = k & 63;
        uint32_t off = c * 16384 + swz(n * 128 + kk * 2);
        *(uint16_t *)(sm + OB2 + off) = packh1(eW2[(size_t)k * 128 + n]);
    }
    if (tid < 128) eb2_s[tid] = eb2[tid];

    const int arow = lane & 15;
    const int ak = (lane >> 4) * 8;
    const int brow = (lane & 7) + 8 * (lane >> 4);
    const int bk = 8 * ((lane >> 3) & 1);

    uint32_t AH[2][4], BH[4][4];
    auto ldA = [&](uint32_t baseA, int koff) {
#pragma unroll
        for (int m = 0; m < 2; m++) {
            uint32_t off = swz((uint32_t)((32 * wm + 16 * m + arow) * 128 + koff * 2));
            ldsm4(AH[m], baseA + off);
        }
    };
    auto ldB = [&](uint32_t baseB, int koff) {
#pragma unroll
        for (int p = 0; p < 4; p++) {
            uint32_t off = swz((uint32_t)((64 * wn + 16 * p + brow) * 128 + koff * 2));
            ldsm4(BH[p], baseB + off);
        }
    };

    for (; tile < ntiles; tile += gridDim.x) {
        const size_t rowbase = (size_t)tile * 256;
        const int nb0 = tile * 8;

        __syncthreads();  // prev tile fully done (incl. weights on iter 0)
        if (tid < 256) mask_s[tid] = mask[rowbase + tid];
        aself_s[tid] = g_aself[(size_t)nb0 * 128 + tid];
        aself_s[tid + 512] = g_aself[(size_t)nb0 * 128 + tid + 512];

        float acc[2][8][4];
#pragma unroll
        for (int m = 0; m < 2; m++)
#pragma unroll
            for (int nt = 0; nt < 8; nt++)
#pragma unroll
                for (int j = 0; j < 4; j++) acc[m][nt][j] = 0.f;

        // ---- GEMM1: K=160 in chunks {64,64,32} ----
#pragma unroll
        for (int c = 0; c < 3; c++) {
            CP_WAIT0();
            __syncthreads();  // staging chunk c visible to all
            if (c < 2) {
#pragma unroll
                for (int i = 0; i < 8; i++) {
                    int q = tid + 512 * i;
                    float4 v = *(const float4 *)(sm + OST + q * 16);
                    uint32_t off = swz((uint32_t)((q >> 4) * 128 + (q & 15) * 8));
                    *(uint2 *)(sm + OAY + off) =
                        make_uint2(packh2(v.x, v.y), packh2(v.z, v.w));
                }
            } else {
#pragma unroll
                for (int i = 0; i < 4; i++) {
                    int q = tid + 512 * i;
                    float4 v = *(const float4 *)(sm + OST + q * 16);
                    uint32_t off = swz((uint32_t)((q >> 3) * 128 + (q & 7) * 8));
                    *(uint2 *)(sm + OAY + off) =
                        make_uint2(packh2(v.x, v.y), packh2(v.z, v.w));
                }
            }
            __syncthreads();  // A ready; staging free
            if (c < 2) issue_cp(tile, c + 1);  // DMA overlaps MMA below
            const int nk = (c == 2) ? 2 : 4;
            const uint32_t bB = sbase + OB1 + c * 16384;
            for (int ks = 0; ks < nk; ks++) {
                ldA(sbase + OAY, ks * 16 + ak);
                ldB(bB, ks * 16 + bk);
#pragma unroll
                for (int m = 0; m < 2; m++)
#pragma unroll
                    for (int p = 0; p < 4; p++) {
                        mma16816(acc[m][2 * p], AH[m], &BH[p][0]);
                        mma16816(acc[m][2 * p + 1], AH[m], &BH[p][2]);
                    }
            }
        }
        __syncthreads();  // GEMM1 done reading A region

        // next tile's chunk-0 DMA overlaps epilogue1 + GEMM2
        {
            int nt2 = tile + gridDim.x;
            if (nt2 < ntiles) issue_cp(nt2, 0);
        }

        // ---- epilogue 1: y = relu(acc + aself) -> Y (fp16, 2 blocks) ----
#pragma unroll
        for (int nt = 0; nt < 8; nt++) {
            int c0 = 64 * wn + 8 * nt + 2 * tig;
            float as0 = aself_s[wm * 128 + c0];
            float as1 = aself_s[wm * 128 + c0 + 1];
            int ckk = c0 & 63;
#pragma unroll
            for (int m = 0; m < 2; m++) {
                int r = 32 * wm + 16 * m + gid;
                float y00 = fmaxf(acc[m][nt][0] + as0, 0.f);
                float y01 = fmaxf(acc[m][nt][1] + as1, 0.f);
                float y10 = fmaxf(acc[m][nt][2] + as0, 0.f);
                float y11 = fmaxf(acc[m][nt][3] + as1, 0.f);
                uint32_t off0 = wn * 32768 + swz((uint32_t)(r * 128 + ckk * 2));
                uint32_t off1 = wn * 32768 + swz((uint32_t)((r + 8) * 128 + ckk * 2));
                *(uint32_t *)(sm + OAY + off0) = packh2(y00, y01);
                *(uint32_t *)(sm + OAY + off1) = packh2(y10, y11);
            }
        }
        __syncthreads();  // Y ready

        // ---- GEMM2: K=128 ----
#pragma unroll
        for (int m = 0; m < 2; m++)
#pragma unroll
            for (int nt = 0; nt < 8; nt++)
#pragma unroll
                for (int j = 0; j < 4; j++) acc[m][nt][j] = 0.f;

        for (int ks = 0; ks < 8; ks++) {
            const int cb = ks >> 2;
            ldA(sbase + OAY + cb * 32768, (ks & 3) * 16 + ak);
            ldB(sbase + OB2 + cb * 16384, (ks & 3) * 16 + bk);
#pragma unroll
            for (int m = 0; m < 2; m++)
#pragma unroll
                for (int p = 0; p < 4; p++) {
                    mma16816(acc[m][2 * p], AH[m], &BH[p][0]);
                    mma16816(acc[m][2 * p + 1], AH[m], &BH[p][2]);
                }
        }

        // ---- epilogue 2: z = relu(acc+eb2); g_mi[node] = sum_k mask*z ----
        {
            float mk[2][2];
#pragma unroll
            for (int m = 0; m < 2; m++) {
                mk[m][0] = mask_s[32 * wm + 16 * m + gid];
                mk[m][1] = mask_s[32 * wm + 16 * m + gid + 8];
            }
#pragma unroll
            for (int nt = 0; nt < 8; nt++) {
                int c0 = 64 * wn + 8 * nt + 2 * tig;
                float eb0 = eb2_s[c0], eb1v = eb2_s[c0 + 1];
                float s0 = 0.f, s1 = 0.f;
#pragma unroll
                for (int m = 0; m < 2; m++) {
                    s0 += mk[m][0] * fmaxf(acc[m][nt][0] + eb0, 0.f) +
                          mk[m][1] * fmaxf(acc[m][nt][2] + eb0, 0.f);
                    s1 += mk[m][0] * fmaxf(acc[m][nt][1] + eb1v, 0.f) +
                          mk[m][1] * fmaxf(acc[m][nt][3] + eb1v, 0.f);
                }
#pragma unroll
                for (int o = 4; o <= 16; o <<= 1) {
                    s0 += __shfl_xor_sync(0xffffffffu, s0, o);
                    s1 += __shfl_xor_sync(0xffffffffu, s1, o);
                }
                if (lane < 4) {
                    g_mi[(size_t)(nb0 + wm) * 128 + c0] = s0;
                    g_mi[(size_t)(nb0 + wm) * 128 + c0 + 1] = s1;
                }
            }
        }
    }
}

// ---------------------------------------------------------------------------
// Kernel 3: node MLP (fp16 HMMA, persistent).
// ---------------------------------------------------------------------------
#define ND_OW1 0
#define ND_OW2 65536
#define ND_OA  98304
#define ND_OB1 163840
#define ND_OB2 164352
#define NODE_SMEM 164864

__global__ __launch_bounds__(256, 1) void node_kernel(
    const float *__restrict__ h_self, const float *__restrict__ nW1,
    const float *__restrict__ nb1, const float *__restrict__ nW2,
    const float *__restrict__ nb2, float *__restrict__ out, int ntiles) {
    char *sm = (char *)smem;
    float *b1s = (float *)(sm + ND_OB1);
    float *b2s = (float *)(sm + ND_OB2);
    const int tid = threadIdx.x;
    const int wid = tid >> 5, lane = tid & 31;
    const int wm = wid & 3, wn = wid >> 2;
    const int gid = lane >> 2, tig = lane & 3;
    const uint32_t sbase = smem_u32(sm);

    for (int idx = tid; idx < 256 * 128; idx += 256) {
        int n = idx & 127, k = idx >> 7;
        int c = k >> 6, kk = k & 63;
        uint32_t off = c * 16384 + swz(n * 128 + kk * 2);
        *(uint16_t *)(sm + ND_OW1 + off) = packh1(nW1[(size_t)k * 128 + n]);
    }
    for (int idx = tid; idx < 128 * 128; idx += 256) {
        int n = idx & 127, k = idx >> 7;
        int c = k >> 6, kk = k & 63;
        uint32_t off = c * 16384 + swz(n * 128 + kk * 2);
        *(uint16_t *)(sm + ND_OW2 + off) = packh1(nW2[(size_t)k * 128 + n]);
    }
    if (tid < 128) {
        b1s[tid] = nb1[tid];
        b2s[tid] = nb2[tid];
    }

    const int arow = lane & 15;
    const int ak = (lane >> 4) * 8;
    const int brow = (lane & 7) + 8 * (lane >> 4);
    const int bk = 8 * ((lane >> 3) & 1);

    uint32_t AH[2][2][4], BH[2][4][4];
    auto ldA = [&](uint32_t baseA, int koff, uint32_t (&AHb)[2][4]) {
#pragma unroll
        for (int m = 0; m < 2; m++) {
            uint32_t off = swz((uint32_t)((32 * wm + 16 * m + arow) * 128 + koff * 2));
            ldsm4(AHb[m], baseA + off);
        }
    };
    auto ldB = [&](uint32_t baseB, int koff, uint32_t (&BHb)[4][4]) {
#pragma unroll
        for (int p = 0; p < 4; p++) {
            uint32_t off = swz((uint32_t)((64 * wn + 16 * p + brow) * 128 + koff * 2));
            ldsm4(BHb[p], baseB + off);
        }
    };

    for (int tile = blockIdx.x; tile < ntiles; tile += gridDim.x) {
        const int row0 = tile * 128;
        __syncthreads();
#pragma unroll
        for (int i = 0; i < 16; i++) {
            int q = tid + 256 * i;
            int r = q >> 5, kc = (q & 31) * 4;
            int grow = row0 + r;
            if (grow > B_ - 1) grow = B_ - 1;
            float4 v = *(const float4 *)(h_self + (size_t)grow * 128 + kc);
            uint32_t off = (kc >> 6) * 16384 + swz((uint32_t)(r * 128 + (kc & 63) * 2));
            *(uint2 *)(sm + ND_OA + off) =
                make_uint2(packh2(v.x, v.y), packh2(v.z, v.w));
        }
#pragma unroll
        for (int i = 0; i < 16; i++) {
            int q = tid + 256 * i;
            int r = q >> 5, kc = (q & 31) * 4;
            int grow = row0 + r;
            if (grow > B_ - 1) grow = B_ - 1;
            float4 v = *(const float4 *)(g_mi + (size_t)grow * 128 + kc);
            uint32_t off =
                (2 + (kc >> 6)) * 16384 + swz((uint32_t)(r * 128 + (kc & 63) * 2));
            *(uint2 *)(sm + ND_OA + off) =
                make_uint2(packh2(v.x, v.y), packh2(v.z, v.w));
        }
        __syncthreads();

        float acc[2][8][4];
#pragma unroll
        for (int m = 0; m < 2; m++)
#pragma unroll
            for (int nt = 0; nt < 8; nt++)
#pragma unroll
                for (int j = 0; j < 4; j++) acc[m][nt][j] = 0.f;

        ldA(sbase + ND_OA, ak, AH[0]);
        ldB(sbase + ND_OW1, bk, BH[0]);
#pragma unroll
        for (int ks = 0; ks < 16; ks++) {
            const int cur = ks & 1, nxt = cur ^ 1;
            if (ks + 1 < 16) {
                const int k2 = ks + 1, cb = k2 >> 2;
                ldA(sbase + ND_OA + cb * 16384, (k2 & 3) * 16 + ak, AH[nxt]);
                ldB(sbase + ND_OW1 + cb * 16384, (k2 & 3) * 16 + bk, BH[nxt]);
            }
#pragma unroll
            for (int m = 0; m < 2; m++)
#pragma unroll
                for (int p = 0; p < 4; p++) {
                    mma16816(acc[m][2 * p], AH[cur][m], &BH[cur][p][0]);
                    mma16816(acc[m][2 * p + 1], AH[cur][m], &BH[cur][p][2]);
                }
        }
        __syncthreads();

#pragma unroll
        for (int nt = 0; nt < 8; nt++) {
            int c0 = 64 * wn + 8 * nt + 2 * tig;
            float bv0 = b1s[c0], bv1 = b1s[c0 + 1];
            int cblk = c0 >> 6, ckk = c0 & 63;
#pragma unroll
            for (int m = 0; m < 2; m++) {
                int r = 32 * wm + 16 * m + gid;
                float y00 = fmaxf(acc[m][nt][0] + bv0, 0.f);
                float y01 = fmaxf(acc[m][nt][1] + bv1, 0.f);
                float y10 = fmaxf(acc[m][nt][2] + bv0, 0.f);
                float y11 = fmaxf(acc[m][nt][3] + bv1, 0.f);
                uint32_t off0 = cblk * 16384 + swz((uint32_t)(r * 128 + ckk * 2));
                uint32_t off1 = cblk * 16384 + swz((uint32_t)((r + 8) * 128 + ckk * 2));
                *(uint32_t *)(sm + ND_OA + off0) = packh2(y00, y01);
                *(uint32_t *)(sm + ND_OA + off1) = packh2(y10, y11);
            }
        }
        __syncthreads();

#pragma unroll
        for (int m = 0; m < 2; m++)
#pragma unroll
            for (int nt = 0; nt < 8; nt++)
#pragma unroll
                for (int j = 0; j < 4; j++) acc[m][nt][j] = 0.f;

        ldA(sbase + ND_OA, ak, AH[0]);
        ldB(sbase + ND_OW2, bk, BH[0]);
#pragma unroll
        for (int ks = 0; ks < 8; ks++) {
            const int cur = ks & 1, nxt = cur ^ 1;
            if (ks + 1 < 8) {
                const int k2 = ks + 1, cb = k2 >> 2;
                ldA(sbase + ND_OA + cb * 16384, (k2 & 3) * 16 + ak, AH[nxt]);
                ldB(sbase + ND_OW2 + cb * 16384, (k2 & 3) * 16 + bk, BH[nxt]);
            }
#pragma unroll
            for (int m = 0; m < 2; m++)
#pragma unroll
                for (int p = 0; p < 4; p++) {
                    mma16816(acc[m][2 * p], AH[cur][m], &BH[cur][p][0]);
                    mma16816(acc[m][2 * p + 1], AH[cur][m], &BH[cur][p][2]);
                }
        }

#pragma unroll
        for (int nt = 0; nt < 8; nt++) {
            int c0 = 64 * wn + 8 * nt + 2 * tig;
            float bv0 = b2s[c0], bv1 = b2s[c0 + 1];
#pragma unroll
            for (int m = 0; m < 2; m++) {
                int r = 32 * wm + 16 * m + gid;
                int grow = row0 + r;
                if (grow < B_) {
                    float2 v = make_float2(fmaxf(acc[m][nt][0] + bv0, 0.f),
                                           fmaxf(acc[m][nt][1] + bv1, 0.f));
                    *(float2 *)(out + (size_t)grow * 128 + c0) = v;
                }
                if (grow + 8 < B_) {
                    float2 v = make_float2(fmaxf(acc[m][nt][2] + bv0, 0.f),
                                           fmaxf(acc[m][nt][3] + bv1, 0.f));
                    *(float2 *)(out + (size_t)(grow + 8) * 128 + c0) = v;
                }
            }
        }
    }
}

// ---------------------------------------------------------------------------
extern "C" void kernel_launch(void *const *d_in, const int *in_sizes, int n_in,
                              void *d_out, int out_size) {
    const float *h_self = (const float *)d_in[0];
    const float *h_nei = (const float *)d_in[1];
    const float *e_ij = (const float *)d_in[2];
    const float *mask = (const float *)d_in[3];
    const float *eW1 = (const float *)d_in[4];
    const float *eb1 = (const float *)d_in[5];
    const float *eW2 = (const float *)d_in[6];
    const float *eb2 = (const float *)d_in[7];
    const float *nW1 = (const float *)d_in[8];
    const float *nb1 = (const float *)d_in[9];
    const float *nW2 = (const float *)d_in[10];
    const float *nb2 = (const float *)d_in[11];
    float *out = (float *)d_out;

    cudaFuncSetAttribute(self_kernel, cudaFuncAttributeMaxDynamicSharedMemorySize,
                         SELF_SMEM);
    cudaFuncSetAttribute(edge_mma_kernel,
                         cudaFuncAttributeMaxDynamicSharedMemorySize, EDGE_SMEM);
    cudaFuncSetAttribute(node_kernel, cudaFuncAttributeMaxDynamicSharedMemorySize,
                         NODE_SMEM);

    int dev = 0, nsm = 148;
    cudaGetDevice(&dev);
    cudaDeviceGetAttribute(&nsm, cudaDevAttrMultiProcessorCount, dev);

    const int tilesAC = (B_ + 127) / 128;     // 391
    const int ntilesB = B_ * K_ / 256;        // 6250 (exact)

    self_kernel<<<nsm, 256, SELF_SMEM>>>(h_self, eW1, eb1, tilesAC);
    edge_mma_kernel<<<nsm, 512, EDGE_SMEM>>>(h_nei, e_ij, mask, eW1, eW2, eb2,
                                             ntilesB);
    node_kernel<<<nsm, 256, NODE_SMEM>>>(h_self, nW1, nb1, nW2, nb2, out, tilesAC);
}

// round 13
// speedup vs baseline: 5.6858x; 1.0183x over previous
#include <cuda_runtime.h>
#include <cuda_fp16.h>
#include <cstdint>
#include <cstddef>

// ---------------------------------------------------------------------------
// MPNN layer, fp32.  B=50000, K=32, D=128, E=32.  ALL GEMMs fp16 HMMA,
// all three kernels persistent with 2-deep cp.async pipelines.
// ---------------------------------------------------------------------------

#define B_  50000
#define K_  32
#define D_  128
#define E_  32

__device__ float g_aself[(size_t)B_ * D_];
__device__ float g_mi[(size_t)B_ * D_];

// ======================= helpers ===========================================
__device__ __forceinline__ uint32_t smem_u32(const void* p) {
    uint32_t a;
    asm("{ .reg .u64 t; cvta.to.shared.u64 t, %1; cvt.u32.u64 %0, t; }"
        : "=r"(a) : "l"(p));
    return a;
}
__device__ __forceinline__ uint32_t swz(uint32_t b) { return b ^ ((b >> 3) & 0x70); }
__device__ __forceinline__ uint32_t swz64(uint32_t b) { return b ^ ((b >> 3) & 0x30); }
__device__ __forceinline__ uint32_t packh2(float a, float b) {
    uint32_t r;
    asm("cvt.rn.f16x2.f32 %0, %1, %2;" : "=r"(r) : "f"(b), "f"(a));
    return r;
}
__device__ __forceinline__ uint16_t packh1(float a) {
    uint16_t r;
    asm("cvt.rn.f16.f32 %0, %1;" : "=h"(r) : "f"(a));
    return r;
}
__device__ __forceinline__ void ldsm4(uint32_t* r, uint32_t addr) {
    asm volatile("ldmatrix.sync.aligned.m8n8.x4.shared.b16 {%0,%1,%2,%3}, [%4];"
                 : "=r"(r[0]), "=r"(r[1]), "=r"(r[2]), "=r"(r[3]) : "r"(addr));
}
__device__ __forceinline__ void mma16816(float* d, const uint32_t* a, const uint32_t* b) {
    asm("mma.sync.aligned.m16n8k16.row.col.f32.f16.f16.f32 "
        "{%0,%1,%2,%3}, {%4,%5,%6,%7}, {%8,%9}, {%0,%1,%2,%3};"
        : "+f"(d[0]), "+f"(d[1]), "+f"(d[2]), "+f"(d[3])
        : "r"(a[0]), "r"(a[1]), "r"(a[2]), "r"(a[3]), "r"(b[0]), "r"(b[1]));
}
#define CP_ASYNC16(dst, src) \
    asm volatile("cp.async.cg.shared.global [%0], [%1], 16;" :: "r"(dst), "l"(src))
#define CP_COMMIT() asm volatile("cp.async.commit_group;" ::: "memory")
#define CP_WAIT0()  asm volatile("cp.async.wait_group 0;" ::: "memory")
#define CP_WAIT1()  asm volatile("cp.async.wait_group 1;" ::: "memory")

extern __shared__ float smem[];

// ---------------------------------------------------------------------------
// Kernel 1: a_self = h_self @ eW1[0:128,:] + eb1  (fp16 HMMA, cp.async pipe)
// ---------------------------------------------------------------------------
#define SW_OW 0        // weights 32768
#define SW_OST 32768   // fp32 staging 65536
#define SW_OA 98304    // A fp16 32768
#define SW_OEB 131072  // 512
#define SELF_SMEM 131584

__global__ __launch_bounds__(256, 1) void self_kernel(
    const float *__restrict__ h_self, const float *__restrict__ eW1,
    const float *__restrict__ eb1, int ntiles) {
    char *sm = (char *)smem;
    float *ebs = (float *)(sm + SW_OEB);
    const int tid = threadIdx.x;
    const int wid = tid >> 5, lane = tid & 31;
    const int wm = wid & 3, wn = wid >> 2;
    const int gid = lane >> 2, tig = lane & 3;
    const uint32_t sbase = smem_u32(sm);

    auto issue_dma = [&](int t2) {
        const int row0 = t2 * 128;
#pragma unroll
        for (int i = 0; i < 16; i++) {
            int q = tid + 256 * i;
            int row = q >> 5, c4 = (q & 31) * 4;
            int grow = row0 + row;
            if (grow > B_ - 1) grow = B_ - 1;
            CP_ASYNC16(sbase + SW_OST + q * 16, h_self + (size_t)grow * 128 + c4);
        }
        CP_COMMIT();
    };

    int tile = blockIdx.x;
    if (tile < ntiles) issue_dma(tile);

    for (int idx = tid; idx < 128 * 128; idx += 256) {
        int n = idx & 127, k = idx >> 7;
        int c = k >> 6, kk = k & 63;
        uint32_t off = c * 16384 + swz(n * 128 + kk * 2);
        *(uint16_t *)(sm + SW_OW + off) = packh1(eW1[(size_t)k * 128 + n]);
    }
    if (tid < 128) ebs[tid] = eb1[tid];

    const int arow = lane & 15;
    const int ak = (lane >> 4) * 8;
    const int brow = (lane & 7) + 8 * (lane >> 4);
    const int bk = 8 * ((lane >> 3) & 1);

    uint32_t AH[2][2][4], BH[2][4][4];
    auto ldA = [&](uint32_t baseA, int koff, uint32_t (&AHb)[2][4]) {
#pragma unroll
        for (int m = 0; m < 2; m++) {
            uint32_t off = swz((uint32_t)((32 * wm + 16 * m + arow) * 128 + koff * 2));
            ldsm4(AHb[m], baseA + off);
        }
    };
    auto ldB = [&](uint32_t baseB, int koff, uint32_t (&BHb)[4][4]) {
#pragma unroll
        for (int p = 0; p < 4; p++) {
            uint32_t off = swz((uint32_t)((64 * wn + 16 * p + brow) * 128 + koff * 2));
            ldsm4(BHb[p], baseB + off);
        }
    };

    for (; tile < ntiles; tile += gridDim.x) {
        const int row0 = tile * 128;
        __syncthreads();  // prev GEMM done reading A; weights ready on iter 0
        CP_WAIT0();
        // convert own staged data -> fp16 blocked
#pragma unroll
        for (int i = 0; i < 16; i++) {
            int q = tid + 256 * i;
            int r = q >> 5, c4 = (q & 31) * 4;
            float4 v = *(const float4 *)(sm + SW_OST + q * 16);
            uint32_t off = (c4 >> 6) * 16384 + swz((uint32_t)(r * 128 + (c4 & 63) * 2));
            *(uint2 *)(sm + SW_OA + off) =
                make_uint2(packh2(v.x, v.y), packh2(v.z, v.w));
        }
        __syncthreads();  // A ready; staging free
        if (tile + gridDim.x < ntiles) issue_dma(tile + gridDim.x);

        float acc[2][8][4];
#pragma unroll
        for (int m = 0; m < 2; m++)
#pragma unroll
            for (int nt = 0; nt < 8; nt++)
#pragma unroll
                for (int j = 0; j < 4; j++) acc[m][nt][j] = 0.f;

        ldA(sbase + SW_OA, ak, AH[0]);
        ldB(sbase + SW_OW, bk, BH[0]);
#pragma unroll
        for (int ks = 0; ks < 8; ks++) {
            const int cur = ks & 1, nxt = cur ^ 1;
            if (ks + 1 < 8) {
                const int k2 = ks + 1, cb = k2 >> 2;
                ldA(sbase + SW_OA + cb * 16384, (k2 & 3) * 16 + ak, AH[nxt]);
                ldB(sbase + SW_OW + cb * 16384, (k2 & 3) * 16 + bk, BH[nxt]);
            }
#pragma unroll
            for (int m = 0; m < 2; m++)
#pragma unroll
                for (int p = 0; p < 4; p++) {
                    mma16816(acc[m][2 * p], AH[cur][m], &BH[cur][p][0]);
                    mma16816(acc[m][2 * p + 1], AH[cur][m], &BH[cur][p][2]);
                }
        }

#pragma unroll
        for (int nt = 0; nt < 8; nt++) {
            int c0 = 64 * wn + 8 * nt + 2 * tig;
            float bv0 = ebs[c0], bv1 = ebs[c0 + 1];
#pragma unroll
            for (int m = 0; m < 2; m++) {
                int r = 32 * wm + 16 * m + gid;
                int grow = row0 + r;
                if (grow < B_) {
                    float2 v = make_float2(acc[m][nt][0] + bv0, acc[m][nt][1] + bv1);
                    *(float2 *)(g_aself + (size_t)grow * 128 + c0) = v;
                }
                if (grow + 8 < B_) {
                    float2 v = make_float2(acc[m][nt][2] + bv0, acc[m][nt][3] + bv1);
                    *(float2 *)(g_aself + (size_t)(grow + 8) * 128 + c0) = v;
                }
            }
        }
    }
}

// ---------------------------------------------------------------------------
// Kernel 2: edge MLP. 512 thr, 256-row tiles, 5 K32 sub-chunks, 2-deep pipe.
// ---------------------------------------------------------------------------
#define OB1 0          // eW1[128:288]^T : 3 x 16384 = 49152
#define OB2 49152      // eW2^T : 2 x 16384 = 32768
#define OST 81920      // dual fp32 staging 2 x 32768 (union: Y 65536)
#define OA  147456     // dual fp16 A sub-chunk 2 x 16384 (SW64)
#define OASELF 180224  // 1024 floats
#define OMASK  184320  // 256 floats
#define OEB2   185344  // 128 floats
#define EDGE_SMEM 185856

__global__ __launch_bounds__(512, 1) void edge_mma_kernel(
    const float *__restrict__ h_nei, const float *__restrict__ e_ij,
    const float *__restrict__ mask, const float *__restrict__ eW1,
    const float *__restrict__ eW2, const float *__restrict__ eb2, int ntiles) {
    char *sm = (char *)smem;
    float *aself_s = (float *)(sm + OASELF);
    float *mask_s = (float *)(sm + OMASK);
    float *eb2_s = (float *)(sm + OEB2);
    const int tid = threadIdx.x;
    const int wid = tid >> 5, lane = tid & 31;
    const int wm = wid & 7, wn = wid >> 3;   // 8 M-groups x 2 N-groups
    const int gid = lane >> 2, tig = lane & 3;
    const uint32_t sbase = smem_u32(sm);

    // DMA one K32 sub-chunk (256 rows x 32 floats = 32 KB) into stage[s&1]
    auto issue_sub = [&](int t2, int s) {
        const size_t rb = (size_t)t2 * 256;
        const uint32_t dst0 = sbase + OST + (uint32_t)(s & 1) * 32768;
#pragma unroll
        for (int i = 0; i < 4; i++) {
            int q = tid + 512 * i;
            int row = q >> 3, c4 = (q & 7) * 4;
            const float *src = (s < 4)
                                   ? (h_nei + (rb + row) * 128 + s * 32 + c4)
                                   : (e_ij + (rb + row) * 32 + c4);
            CP_ASYNC16(dst0 + q * 16, src);
        }
        CP_COMMIT();
    };

    int tile = blockIdx.x;
    if (tile < ntiles) { issue_sub(tile, 0); issue_sub(tile, 1); }

    // one-time: weights -> fp16 [n][k] blocked (overlaps prologue DMA)
    for (int idx = tid; idx < 160 * 128; idx += 512) {
        int n = idx & 127, k = idx >> 7;
        int c = k >> 6, kk = k & 63;
        uint32_t off = c * 16384 + swz(n * 128 + kk * 2);
        *(uint16_t *)(sm + OB1 + off) = packh1(eW1[(size_t)(128 + k) * 128 + n]);
    }
    for (int idx = tid; idx < 128 * 128; idx += 512) {
        int n = idx & 127, k = idx >> 7;
        int c = k >> 6, kk = k & 63;
        uint32_t off = c * 16384 + swz(n * 128 + kk * 2);
        *(uint16_t *)(sm + OB2 + off) = packh1(eW2[(size_t)k * 128 + n]);
    }
    if (tid < 128) eb2_s[tid] = eb2[tid];

    const int arow = lane & 15;
    const int ak = (lane >> 4) * 8;
    const int brow = (lane & 7) + 8 * (lane >> 4);
    const int bk = 8 * ((lane >> 3) & 1);

    uint32_t AH[2][4], BH[4][4];
    auto ldA64 = [&](uint32_t baseA, int koff) {
#pragma unroll
        for (int m = 0; m < 2; m++) {
            uint32_t off = swz64((uint32_t)((32 * wm + 16 * m + arow) * 64 + koff * 2));
            ldsm4(AH[m], baseA + off);
        }
    };
    auto ldA128 = [&](uint32_t baseA, int koff) {
#pragma unroll
        for (int m = 0; m < 2; m++) {
            uint32_t off = swz((uint32_t)((32 * wm + 16 * m + arow) * 128 + koff * 2));
            ldsm4(AH[m], baseA + off);
        }
    };
    auto ldB128 = [&](uint32_t baseB, int koff) {
#pragma unroll
        for (int p = 0; p < 4; p++) {
            uint32_t off = swz((uint32_t)((64 * wn + 16 * p + brow) * 128 + koff * 2));
            ldsm4(BH[p], baseB + off);
        }
    };

    for (; tile < ntiles; tile += gridDim.x) {
        const size_t rowbase = (size_t)tile * 256;
        const int nb0 = tile * 8;

        __syncthreads();  // prev tile fully done (weights on iter 0)
        if (tid < 256) mask_s[tid] = mask[rowbase + tid];
        aself_s[tid] = g_aself[(size_t)nb0 * 128 + tid];
        aself_s[tid + 512] = g_aself[(size_t)nb0 * 128 + tid + 512];

        float acc[2][8][4];
#pragma unroll
        for (int m = 0; m < 2; m++)
#pragma unroll
            for (int nt = 0; nt < 8; nt++)
#pragma unroll
                for (int j = 0; j < 4; j++) acc[m][nt][j] = 0.f;

        // ---- GEMM1: 5 sub-chunks of K=32, 2-deep DMA pipeline ----
#pragma unroll
        for (int s = 0; s < 5; s++) {
            if (s < 4) { CP_WAIT1(); } else { CP_WAIT0(); }
            // convert own-thread staged data -> fp16 SW64 A[s&1]
            {
                const uint32_t st0 = sbase + OST + (uint32_t)(s & 1) * 32768;
                const uint32_t ad0 = sbase + OA + (uint32_t)(s & 1) * 16384;
#pragma unroll
                for (int i = 0; i < 4; i++) {
                    int q = tid + 512 * i;
                    int row = q >> 3, c4 = (q & 7) * 4;
                    float4 v = *(const float4 *)(sm + (st0 - sbase) + q * 16);
                    uint32_t off = swz64((uint32_t)(row * 64 + c4 * 2));
                    *(uint2 *)(sm + (ad0 - sbase) + off) =
                        make_uint2(packh2(v.x, v.y), packh2(v.z, v.w));
                }
            }
            __syncthreads();  // A[s&1] ready; stage[s&1] free
            if (s < 3) issue_sub(tile, s + 2);  // DMA overlaps MMA
            const uint32_t aB = sbase + OA + (uint32_t)(s & 1) * 16384;
#pragma unroll
            for (int ks = 0; ks < 2; ks++) {
                const int g = 2 * s + ks;
                ldA64(aB, ks * 16 + ak);
                ldB128(sbase + OB1 + (g >> 2) * 16384, (g & 3) * 16 + bk);
#pragma unroll
                for (int m = 0; m < 2; m++)
#pragma unroll
                    for (int p = 0; p < 4; p++) {
                        mma16816(acc[m][2 * p], AH[m], &BH[p][0]);
                        mma16816(acc[m][2 * p + 1], AH[m], &BH[p][2]);
                    }
            }
        }

        // ---- epilogue 1: y = relu(acc + aself) -> Y (fp16, OST region) ----
#pragma unroll
        for (int nt = 0; nt < 8; nt++) {
            int c0 = 64 * wn + 8 * nt + 2 * tig;
            float as0 = aself_s[wm * 128 + c0];
            float as1 = aself_s[wm * 128 + c0 + 1];
            int ckk = c0 & 63;
#pragma unroll
            for (int m = 0; m < 2; m++) {
                int r = 32 * wm + 16 * m + gid;
                float y00 = fmaxf(acc[m][nt][0] + as0, 0.f);
                float y01 = fmaxf(acc[m][nt][1] + as1, 0.f);
                float y10 = fmaxf(acc[m][nt][2] + as0, 0.f);
                float y11 = fmaxf(acc[m][nt][3] + as1, 0.f);
                uint32_t off0 = wn * 32768 + swz((uint32_t)(r * 128 + ckk * 2));
                uint32_t off1 = wn * 32768 + swz((uint32_t)((r + 8) * 128 + ckk * 2));
                *(uint32_t *)(sm + OST + off0) = packh2(y00, y01);
                *(uint32_t *)(sm + OST + off1) = packh2(y10, y11);
            }
        }
        __syncthreads();  // Y ready

        // ---- GEMM2: K=128 ----
#pragma unroll
        for (int m = 0; m < 2; m++)
#pragma unroll
            for (int nt = 0; nt < 8; nt++)
#pragma unroll
                for (int j = 0; j < 4; j++) acc[m][nt][j] = 0.f;

        for (int ks = 0; ks < 8; ks++) {
            const int cb = ks >> 2;
            ldA128(sbase + OST + cb * 32768, (ks & 3) * 16 + ak);
            ldB128(sbase + OB2 + cb * 16384, (ks & 3) * 16 + bk);
#pragma unroll
            for (int m = 0; m < 2; m++)
#pragma unroll
                for (int p = 0; p < 4; p++) {
                    mma16816(acc[m][2 * p], AH[m], &BH[p][0]);
                    mma16816(acc[m][2 * p + 1], AH[m], &BH[p][2]);
                }
        }
        __syncthreads();  // all GEMM2 reads of Y done -> stage reusable

        // next tile's first two sub-chunk DMAs overlap epilogue 2
        if (tile + gridDim.x < ntiles) {
            issue_sub(tile + gridDim.x, 0);
            issue_sub(tile + gridDim.x, 1);
        }

        // ---- epilogue 2: z = relu(acc+eb2); g_mi[node] = sum mask*z ----
        {
            float mk[2][2];
#pragma unroll
            for (int m = 0; m < 2; m++) {
                mk[m][0] = mask_s[32 * wm + 16 * m + gid];
                mk[m][1] = mask_s[32 * wm + 16 * m + gid + 8];
            }
#pragma unroll
            for (int nt = 0; nt < 8; nt++) {
                int c0 = 64 * wn + 8 * nt + 2 * tig;
                float eb0 = eb2_s[c0], eb1v = eb2_s[c0 + 1];
                float s0 = 0.f, s1 = 0.f;
#pragma unroll
                for (int m = 0; m < 2; m++) {
                    s0 += mk[m][0] * fmaxf(acc[m][nt][0] + eb0, 0.f) +
                          mk[m][1] * fmaxf(acc[m][nt][2] + eb0, 0.f);
                    s1 += mk[m][0] * fmaxf(acc[m][nt][1] + eb1v, 0.f) +
                          mk[m][1] * fmaxf(acc[m][nt][3] + eb1v, 0.f);
                }
#pragma unroll
                for (int o = 4; o <= 16; o <<= 1) {
                    s0 += __shfl_xor_sync(0xffffffffu, s0, o);
                    s1 += __shfl_xor_sync(0xffffffffu, s1, o);
                }
                if (lane < 4) {
                    g_mi[(size_t)(nb0 + wm) * 128 + c0] = s0;
                    g_mi[(size_t)(nb0 + wm) * 128 + c0 + 1] = s1;
                }
            }
        }
    }
}

// ---------------------------------------------------------------------------
// Kernel 3: node MLP (fp16 HMMA, staged halves pipeline)
// ---------------------------------------------------------------------------
#define ND_OW1 0        // 65536
#define ND_OW2 65536    // 32768
#define ND_OA  98304    // 65536 (blocks 0-1: h_self / Y; 2-3: g_mi)
#define ND_OST 163840   // 65536 fp32 staging (one half at a time)
#define ND_OB1 229376
#define ND_OB2 229888
#define NODE_SMEM 230400

__global__ __launch_bounds__(256, 1) void node_kernel(
    const float *__restrict__ h_self, const float *__restrict__ nW1,
    const float *__restrict__ nb1, const float *__restrict__ nW2,
    const float *__restrict__ nb2, float *__restrict__ out, int ntiles) {
    char *sm = (char *)smem;
    float *b1s = (float *)(sm + ND_OB1);
    float *b2s = (float *)(sm + ND_OB2);
    const int tid = threadIdx.x;
    const int wid = tid >> 5, lane = tid & 31;
    const int wm = wid & 3, wn = wid >> 2;
    const int gid = lane >> 2, tig = lane & 3;
    const uint32_t sbase = smem_u32(sm);

    auto issue_half = [&](int t2, int h) {
        const int row0 = t2 * 128;
        const float *srcb = h ? g_mi : h_self;
#pragma unroll
        for (int i = 0; i < 16; i++) {
            int q = tid + 256 * i;
            int row = q >> 5, c4 = (q & 31) * 4;
            int grow = row0 + row;
            if (grow > B_ - 1) grow = B_ - 1;
            CP_ASYNC16(sbase + ND_OST + q * 16, srcb + (size_t)grow * 128 + c4);
        }
        CP_COMMIT();
    };

    int tile = blockIdx.x;
    if (tile < ntiles) issue_half(tile, 0);

    for (int idx = tid; idx < 256 * 128; idx += 256) {
        int n = idx & 127, k = idx >> 7;
        int c = k >> 6, kk = k & 63;
        uint32_t off = c * 16384 + swz(n * 128 + kk * 2);
        *(uint16_t *)(sm + ND_OW1 + off) = packh1(nW1[(size_t)k * 128 + n]);
    }
    for (int idx = tid; idx < 128 * 128; idx += 256) {
        int n = idx & 127, k = idx >> 7;
        int c = k >> 6, kk = k & 63;
        uint32_t off = c * 16384 + swz(n * 128 + kk * 2);
        *(uint16_t *)(sm + ND_OW2 + off) = packh1(nW2[(size_t)k * 128 + n]);
    }
    if (tid < 128) {
        b1s[tid] = nb1[tid];
        b2s[tid] = nb2[tid];
    }

    const int arow = lane & 15;
    const int ak = (lane >> 4) * 8;
    const int brow = (lane & 7) + 8 * (lane >> 4);
    const int bk = 8 * ((lane >> 3) & 1);

    uint32_t AH[2][4], BH[4][4];
    auto ldA = [&](uint32_t baseA, int koff) {
#pragma unroll
        for (int m = 0; m < 2; m++) {
            uint32_t off = swz((uint32_t)((32 * wm + 16 * m + arow) * 128 + koff * 2));
            ldsm4(AH[m], baseA + off);
        }
    };
    auto ldB = [&](uint32_t baseB, int koff) {
#pragma unroll
        for (int p = 0; p < 4; p++) {
            uint32_t off = swz((uint32_t)((64 * wn + 16 * p + brow) * 128 + koff * 2));
            ldsm4(BH[p], baseB + off);
        }
    };
    auto convert_half = [&](int h) {
#pragma unroll
        for (int i = 0; i < 16; i++) {
            int q = tid + 256 * i;
            int r = q >> 5, c4 = (q & 31) * 4;
            float4 v = *(const float4 *)(sm + ND_OST + q * 16);
            uint32_t off = (2 * h + (c4 >> 6)) * 16384 +
                           swz((uint32_t)(r * 128 + (c4 & 63) * 2));
            *(uint2 *)(sm + ND_OA + off) =
                make_uint2(packh2(v.x, v.y), packh2(v.z, v.w));
        }
    };

    for (; tile < ntiles; tile += gridDim.x) {
        const int row0 = tile * 128;
        __syncthreads();  // prev tile done with OA (weights on iter 0)
        CP_WAIT0();       // h_self half staged
        convert_half(0);
        __syncthreads();
        issue_half(tile, 1);  // g_mi DMA overlaps first 8 ksteps

        float acc[2][8][4];
#pragma unroll
        for (int m = 0; m < 2; m++)
#pragma unroll
            for (int nt = 0; nt < 8; nt++)
#pragma unroll
                for (int j = 0; j < 4; j++) acc[m][nt][j] = 0.f;

        // GEMM1 ksteps 0-7 (h_self half)
        for (int ks = 0; ks < 8; ks++) {
            const int cb = ks >> 2;
            ldA(sbase + ND_OA + cb * 16384, (ks & 3) * 16 + ak);
            ldB(sbase + ND_OW1 + cb * 16384, (ks & 3) * 16 + bk);
#pragma unroll
            for (int m = 0; m < 2; m++)
#pragma unroll
                for (int p = 0; p < 4; p++) {
                    mma16816(acc[m][2 * p], AH[m], &BH[p][0]);
                    mma16816(acc[m][2 * p + 1], AH[m], &BH[p][2]);
                }
        }
        CP_WAIT0();       // g_mi half staged
        convert_half(1);
        __syncthreads();
        if (tile + gridDim.x < ntiles) issue_half(tile + gridDim.x, 0);

        // GEMM1 ksteps 8-15 (g_mi half)
        for (int ks = 8; ks < 16; ks++) {
            const int cb = ks >> 2;
            ldA(sbase + ND_OA + cb * 16384, (ks & 3) * 16 + ak);
            ldB(sbase + ND_OW1 + cb * 16384, (ks & 3) * 16 + bk);
#pragma unroll
            for (int m = 0; m < 2; m++)
#pragma unroll
                for (int p = 0; p < 4; p++) {
                    mma16816(acc[m][2 * p], AH[m], &BH[p][0]);
                    mma16816(acc[m][2 * p + 1], AH[m], &BH[p][2]);
                }
        }
        __syncthreads();  // all GEMM1 reads done before Y overwrites blocks 0-1

        // epilogue 1: h1 = relu(acc + b1) -> blocks 0-1
#pragma unroll
        for (int nt = 0; nt < 8; nt++) {
            int c0 = 64 * wn + 8 * nt + 2 * tig;
            float bv0 = b1s[c0], bv1 = b1s[c0 + 1];
            int cblk = c0 >> 6, ckk = c0 & 63;
#pragma unroll
            for (int m = 0; m < 2; m++) {
                int r = 32 * wm + 16 * m + gid;
                float y00 = fmaxf(acc[m][nt][0] + bv0, 0.f);
                float y01 = fmaxf(acc[m][nt][1] + bv1, 0.f);
                float y10 = fmaxf(acc[m][nt][2] + bv0, 0.f);
                float y11 = fmaxf(acc[m][nt][3] + bv1, 0.f);
                uint32_t off0 = cblk * 16384 + swz((uint32_t)(r * 128 + ckk * 2));
                uint32_t off1 = cblk * 16384 + swz((uint32_t)((r + 8) * 128 + ckk * 2));
                *(uint32_t *)(sm + ND_OA + off0) = packh2(y00, y01);
                *(uint32_t *)(sm + ND_OA + off1) = packh2(y10, y11);
            }
        }
        __syncthreads();

        // GEMM2: K=128
#pragma unroll
        for (int m = 0; m < 2; m++)
#pragma unroll
            for (int nt = 0; nt < 8; nt++)
#pragma unroll
                for (int j = 0; j < 4; j++) acc[m][nt][j] = 0.f;

        for (int ks = 0; ks < 8; ks++) {
            const int cb = ks >> 2;
            ldA(sbase + ND_OA + cb * 16384, (ks & 3) * 16 + ak);
            ldB(sbase + ND_OW2 + cb * 16384, (ks & 3) * 16 + bk);
#pragma unroll
            for (int m = 0; m < 2; m++)
#pragma unroll
                for (int p = 0; p < 4; p++) {
                    mma16816(acc[m][2 * p], AH[m], &BH[p][0]);
                    mma16816(acc[m][2 * p + 1], AH[m], &BH[p][2]);
                }
        }

        // epilogue 2: out = relu(acc + b2)
#pragma unroll
        for (int nt = 0; nt < 8; nt++) {
            int c0 = 64 * wn + 8 * nt + 2 * tig;
            float bv0 = b2s[c0], bv1 = b2s[c0 + 1];
#pragma unroll
            for (int m = 0; m < 2; m++) {
                int r = 32 * wm + 16 * m + gid;
                int grow = row0 + r;
                if (grow < B_) {
                    float2 v = make_float2(fmaxf(acc[m][nt][0] + bv0, 0.f),
                                           fmaxf(acc[m][nt][1] + bv1, 0.f));
                    *(float2 *)(out + (size_t)grow * 128 + c0) = v;
                }
                if (grow + 8 < B_) {
                    float2 v = make_float2(fmaxf(acc[m][nt][2] + bv0, 0.f),
                                           fmaxf(acc[m][nt][3] + bv1, 0.f));
                    *(float2 *)(out + (size_t)(grow + 8) * 128 + c0) = v;
                }
            }
        }
    }
}

// ---------------------------------------------------------------------------
extern "C" void kernel_launch(void *const *d_in, const int *in_sizes, int n_in,
                              void *d_out, int out_size) {
    const float *h_self = (const float *)d_in[0];
    const float *h_nei = (const float *)d_in[1];
    const float *e_ij = (const float *)d_in[2];
    const float *mask = (const float *)d_in[3];
    const float *eW1 = (const float *)d_in[4];
    const float *eb1 = (const float *)d_in[5];
    const float *eW2 = (const float *)d_in[6];
    const float *eb2 = (const float *)d_in[7];
    const float *nW1 = (const float *)d_in[8];
    const float *nb1 = (const float *)d_in[9];
    const float *nW2 = (const float *)d_in[10];
    const float *nb2 = (const float *)d_in[11];
    float *out = (float *)d_out;

    cudaFuncSetAttribute(self_kernel, cudaFuncAttributeMaxDynamicSharedMemorySize,
                         SELF_SMEM);
    cudaFuncSetAttribute(edge_mma_kernel,
                         cudaFuncAttributeMaxDynamicSharedMemorySize, EDGE_SMEM);
    cudaFuncSetAttribute(node_kernel, cudaFuncAttributeMaxDynamicSharedMemorySize,
                         NODE_SMEM);

    int dev = 0, nsm = 148;
    cudaGetDevice(&dev);
    cudaDeviceGetAttribute(&nsm, cudaDevAttrMultiProcessorCount, dev);

    const int tilesAC = (B_ + 127) / 128;   // 391
    const int ntilesB = B_ * K_ / 256;      // 6250

    self_kernel<<<nsm, 256, SELF_SMEM>>>(h_self, eW1, eb1, tilesAC);
    edge_mma_kernel<<<nsm, 512, EDGE_SMEM>>>(h_nei, e_ij, mask, eW1, eW2, eb2,
                                             ntilesB);
    node_kernel<<<nsm, 256, NODE_SMEM>>>(h_self, nW1, nb1, nW2, nb2, out, tilesAC);
}